// round 10
// baseline (speedup 1.0000x reference)
#include <cuda_runtime.h>
#include <float.h>

#define S_    1600
#define DIM_  384
#define NH_   6
#define DH_   64
#define INNER_ 384
#define HID_  1536
#define NL_   6
#define GW_   40
#define TOPK_ 32
#define SCALE_ 0.05103103630798288f   // 384^-0.5

// ---------------- device scratch ----------------
__device__ float g_h[S_*DIM_];
__device__ float g_n[S_*DIM_];
__device__ float g_q[NH_*S_*DH_];
__device__ float g_k[NH_*S_*DH_];
__device__ float g_v[NH_*S_*DH_];
__device__ float g_pb[NH_*S_*64];
__device__ float g_rbT[64*64];
__device__ unsigned g_skey[(long long)NH_*S_*S_];
__device__ float g_att[S_*INNER_];
__device__ float g_ff1[S_*HID_];
__device__ float g_part[3][S_*DIM_];     // split-K partials for Wo / FF2

// ---------------- tf32 helpers ----------------
__device__ __forceinline__ unsigned f2tf32(float x) {
    unsigned r;
    asm("cvt.rna.tf32.f32 %0, %1;" : "=r"(r) : "f"(x));
    return r;
}
__device__ __forceinline__ void mma_tf32(float* c, const unsigned* a, const unsigned* b) {
    asm volatile(
        "mma.sync.aligned.m16n8k8.row.col.f32.tf32.tf32.f32 "
        "{%0,%1,%2,%3}, {%4,%5,%6,%7}, {%8,%9}, {%0,%1,%2,%3};"
        : "+f"(c[0]), "+f"(c[1]), "+f"(c[2]), "+f"(c[3])
        : "r"(a[0]), "r"(a[1]), "r"(a[2]), "r"(a[3]), "r"(b[0]), "r"(b[1]));
}

// ---------------- trivial kernels ----------------
__global__ void init_h_kernel(const float* __restrict__ x) {
    int i = blockIdx.x * blockDim.x + threadIdx.x;
    if (i < S_*DIM_) g_h[i] = x[i];
}
__global__ void write_out_sum(float* __restrict__ out) {
    int i = blockIdx.x * blockDim.x + threadIdx.x;
    if (i < S_*DIM_) out[i] = g_h[i] + g_part[0][i] + g_part[1][i] + g_part[2][i];
}
__global__ void rbT_kernel(const float* __restrict__ rb) {
    int i = blockIdx.x * blockDim.x + threadIdx.x;
    if (i < 64*64) {
        int d = i >> 6, m = i & 63;
        g_rbT[d*64 + m] = (m < 49) ? rb[m*64 + d] : 0.f;
    }
}

// ---------------- LayerNorm (plain: reads g_h) ----------------
__global__ void ln_kernel(const float* __restrict__ gamma, const float* __restrict__ beta) {
    int row = blockIdx.x;
    const float* x = g_h + row * DIM_;
    float s = 0.f, s2 = 0.f;
    for (int i = threadIdx.x; i < DIM_; i += blockDim.x) { float v = x[i]; s += v; s2 += v*v; }
    for (int o = 16; o; o >>= 1) {
        s  += __shfl_xor_sync(0xffffffffu, s,  o);
        s2 += __shfl_xor_sync(0xffffffffu, s2, o);
    }
    __shared__ float rs[4], rs2[4];
    int w = threadIdx.x >> 5;
    if ((threadIdx.x & 31) == 0) { rs[w] = s; rs2[w] = s2; }
    __syncthreads();
    s  = rs[0]  + rs[1]  + rs[2]  + rs[3];
    s2 = rs2[0] + rs2[1] + rs2[2] + rs2[3];
    float mean = s * (1.f / DIM_);
    float var  = s2 * (1.f / DIM_) - mean * mean;
    float inv  = rsqrtf(var + 1e-5f);
    for (int i = threadIdx.x; i < DIM_; i += blockDim.x)
        g_n[row*DIM_ + i] = (x[i] - mean) * inv * gamma[i] + beta[i];
}

// ---------------- LayerNorm fused with split-K reduction: h += p0+p1+p2, then LN ----------------
__global__ void __launch_bounds__(128) ln_sum3(const float* __restrict__ gamma,
                                               const float* __restrict__ beta) {
    int row = blockIdx.x;
    int base = row * DIM_;
    float xr[3];
    float s = 0.f, s2 = 0.f;
#pragma unroll
    for (int c = 0; c < 3; c++) {
        int i = threadIdx.x + c * 128;
        float v = g_h[base + i] + g_part[0][base + i] + g_part[1][base + i] + g_part[2][base + i];
        xr[c] = v; s += v; s2 += v*v;
    }
    for (int o = 16; o; o >>= 1) {
        s  += __shfl_xor_sync(0xffffffffu, s,  o);
        s2 += __shfl_xor_sync(0xffffffffu, s2, o);
    }
    __shared__ float rs[4], rs2[4];
    int w = threadIdx.x >> 5;
    if ((threadIdx.x & 31) == 0) { rs[w] = s; rs2[w] = s2; }
    __syncthreads();
    s  = rs[0]  + rs[1]  + rs[2]  + rs[3];
    s2 = rs2[0] + rs2[1] + rs2[2] + rs2[3];
    float mean = s * (1.f / DIM_);
    float var  = s2 * (1.f / DIM_) - mean * mean;
    float inv  = rsqrtf(var + 1e-5f);
#pragma unroll
    for (int c = 0; c < 3; c++) {
        int i = threadIdx.x + c * 128;
        g_h[base + i] = xr[c];
        g_n[base + i] = (xr[c] - mean) * inv * gamma[i] + beta[i];
    }
}

// ========== double-buffered 64x64x16 SGEMM, 4x4 register tiles ==========
// MODE 0: A=g_n (lda=DIM),  QKV scatter -> g_q/g_k/g_v
// MODE 1: A=g_att (lda=INNER), split-K: g_part[z] = acc          (Wo)
// MODE 2: A=g_n (lda=DIM),  g_ff1 = leaky_relu(acc+bias, 0.2)    (FF1)
// MODE 3: A=g_ff1 (lda=HID), split-K: g_part[z] = acc (+bias@z0) (FF2)
// K parameter = per-chunk depth; chunk offset = blockIdx.z * K.
template<int MODE>
__global__ void __launch_bounds__(256) gemm64db(const float* __restrict__ B,
                                                const float* __restrict__ bias,
                                                int N, int K) {
    const float* A = (MODE == 0 || MODE == 2) ? g_n : (MODE == 1 ? g_att : g_ff1);
    const int lda = (MODE == 3) ? HID_ : ((MODE == 1) ? INNER_ : DIM_);
    const int koff = blockIdx.z * K;
    __shared__ __align__(16) float As[2][16][68];
    __shared__ __align__(16) float Bs[2][16][68];
    int tid = threadIdx.x;
    int tx = tid & 15, ty = tid >> 4;
    int m0 = blockIdx.y * 64, n0 = blockIdx.x * 64;
    int arow = tid >> 2, acol = (tid & 3) * 4;
    int brow = tid >> 4, bcol = (tid & 15) * 4;
    const int nk = K >> 4;
    {
        float4 av = *reinterpret_cast<const float4*>(A + (size_t)(m0 + arow) * lda + koff + acol);
        As[0][acol+0][arow] = av.x; As[0][acol+1][arow] = av.y;
        As[0][acol+2][arow] = av.z; As[0][acol+3][arow] = av.w;
        float4 bv = *reinterpret_cast<const float4*>(B + (size_t)(koff + brow) * N + n0 + bcol);
        *reinterpret_cast<float4*>(&Bs[0][brow][bcol]) = bv;
    }
    __syncthreads();
    float acc[4][4] = {};
    for (int t = 0; t < nk; t++) {
        int cur = t & 1, nxt = cur ^ 1;
        float4 av, bv;
        bool more = (t + 1 < nk);
        if (more) {
            int k0 = (t + 1) << 4;
            av = *reinterpret_cast<const float4*>(A + (size_t)(m0 + arow) * lda + koff + k0 + acol);
            bv = *reinterpret_cast<const float4*>(B + (size_t)(koff + k0 + brow) * N + n0 + bcol);
        }
#pragma unroll
        for (int kk = 0; kk < 16; kk++) {
            float4 a4 = *reinterpret_cast<const float4*>(&As[cur][kk][ty*4]);
            float4 b4 = *reinterpret_cast<const float4*>(&Bs[cur][kk][tx*4]);
            float ar[4] = {a4.x, a4.y, a4.z, a4.w};
            float br[4] = {b4.x, b4.y, b4.z, b4.w};
#pragma unroll
            for (int i = 0; i < 4; i++)
#pragma unroll
                for (int j = 0; j < 4; j++)
                    acc[i][j] = fmaf(ar[i], br[j], acc[i][j]);
        }
        if (more) {
            As[nxt][acol+0][arow] = av.x; As[nxt][acol+1][arow] = av.y;
            As[nxt][acol+2][arow] = av.z; As[nxt][acol+3][arow] = av.w;
            *reinterpret_cast<float4*>(&Bs[nxt][brow][bcol]) = bv;
        }
        __syncthreads();
    }
#pragma unroll
    for (int i = 0; i < 4; i++) {
        int m = m0 + ty*4 + i;
#pragma unroll
        for (int j = 0; j < 4; j++) {
            int n = n0 + tx*4 + j;
            float v = acc[i][j];
            if (MODE == 0) {
                int idx = n / 3, r = n - idx * 3;
                int hh = idx >> 6, d = idx & 63;
                float* dst = (r == 0) ? g_q : (r == 1) ? g_k : g_v;
                dst[(hh * S_ + m) * DH_ + d] = v;
            } else if (MODE == 1) {
                g_part[blockIdx.z][m * DIM_ + n] = v;
            } else if (MODE == 2) {
                float t2 = v + bias[n];
                g_ff1[m * HID_ + n] = t2 > 0.f ? t2 : 0.2f * t2;
            } else {
                g_part[blockIdx.z][m * DIM_ + n] = v + (blockIdx.z == 0 ? bias[n] : 0.f);
            }
        }
    }
}

// ---------------- pb GEMM: g_pb[9600x64] = g_q @ g_rbT ----------------
__global__ void __launch_bounds__(256) pb_gemm() {
    const float* A = g_q;
    const float* B = g_rbT;
    __shared__ __align__(16) float As[16][68];
    __shared__ __align__(16) float Bs[16][68];
    int tid = threadIdx.x;
    int tx = tid & 15, ty = tid >> 4;
    int m0 = blockIdx.y * 64;
    int arow = tid >> 2, acol = (tid & 3) * 4;
    int brow = tid >> 4, bcol = (tid & 15) * 4;
    float acc[4][4] = {};
    for (int k0 = 0; k0 < 64; k0 += 16) {
        float4 av = *reinterpret_cast<const float4*>(A + (size_t)(m0 + arow) * 64 + k0 + acol);
        As[acol+0][arow] = av.x; As[acol+1][arow] = av.y;
        As[acol+2][arow] = av.z; As[acol+3][arow] = av.w;
        float4 bv = *reinterpret_cast<const float4*>(B + (size_t)(k0 + brow) * 64 + bcol);
        *reinterpret_cast<float4*>(&Bs[brow][bcol]) = bv;
        __syncthreads();
#pragma unroll
        for (int kk = 0; kk < 16; kk++) {
            float4 a4 = *reinterpret_cast<const float4*>(&As[kk][ty*4]);
            float4 b4 = *reinterpret_cast<const float4*>(&Bs[kk][tx*4]);
            float ar[4] = {a4.x, a4.y, a4.z, a4.w};
            float br[4] = {b4.x, b4.y, b4.z, b4.w};
#pragma unroll
            for (int i = 0; i < 4; i++)
#pragma unroll
                for (int j = 0; j < 4; j++)
                    acc[i][j] = fmaf(ar[i], br[j], acc[i][j]);
        }
        __syncthreads();
    }
#pragma unroll
    for (int i = 0; i < 4; i++)
#pragma unroll
        for (int j = 0; j < 4; j++)
            g_pb[(m0 + ty*4 + i) * 64 + tx*4 + j] = acc[i][j];
}

// ---------------- scores via split-tf32 MMA ----------------
__global__ void __launch_bounds__(256) scores_mma() {
    int h = blockIdx.z;
    const float* Q  = g_q + (size_t)h * S_ * DH_;
    const float* Km = g_k + (size_t)h * S_ * DH_;
    __shared__ __align__(16) float Qs[64][68];
    __shared__ __align__(16) float Ks[64][68];
    int tid = threadIdx.x;
    int m0 = blockIdx.y * 64, n0 = blockIdx.x * 64;
#pragma unroll
    for (int i = 0; i < 4; i++) {
        int e = tid + i * 256;
        int row = e >> 4, c = (e & 15) * 4;
        *reinterpret_cast<float4*>(&Qs[row][c]) =
            *reinterpret_cast<const float4*>(Q + (size_t)(m0 + row) * DH_ + c);
        *reinterpret_cast<float4*>(&Ks[row][c]) =
            *reinterpret_cast<const float4*>(Km + (size_t)(n0 + row) * DH_ + c);
    }
    __syncthreads();

    int wid = tid >> 5, lane = tid & 31;
    int wy = wid >> 1, wx = wid & 1;
    int gr = lane >> 2, tg = lane & 3;

    float acc[4][4] = {};
#pragma unroll
    for (int k0 = 0; k0 < 64; k0 += 8) {
        int ar = wy*16 + gr;
        float a[4];
        a[0] = Qs[ar    ][k0 + tg];
        a[1] = Qs[ar + 8][k0 + tg];
        a[2] = Qs[ar    ][k0 + tg + 4];
        a[3] = Qs[ar + 8][k0 + tg + 4];
        unsigned ah[4], al[4];
#pragma unroll
        for (int i = 0; i < 4; i++) {
            ah[i] = f2tf32(a[i]);
            al[i] = f2tf32(a[i] - __uint_as_float(ah[i]));
        }
#pragma unroll
        for (int t = 0; t < 4; t++) {
            int bn = wx*32 + t*8 + gr;
            float b0 = Ks[bn][k0 + tg];
            float b1 = Ks[bn][k0 + tg + 4];
            unsigned bh[2], bl[2];
            bh[0] = f2tf32(b0); bl[0] = f2tf32(b0 - __uint_as_float(bh[0]));
            bh[1] = f2tf32(b1); bl[1] = f2tf32(b1 - __uint_as_float(bh[1]));
            mma_tf32(acc[t], ah, bh);
            mma_tf32(acc[t], ah, bl);
            mma_tf32(acc[t], al, bh);
        }
    }
#pragma unroll
    for (int rr = 0; rr < 2; rr++) {
        int q = m0 + wy*16 + gr + rr*8;
        int qv = q / GW_, qh = q - qv * GW_;
        const float* pbq = g_pb + ((size_t)h * S_ + q) * 64;
        float pb0 = pbq[0];
        unsigned* srow = g_skey + ((size_t)h * S_ + q) * S_;
#pragma unroll
        for (int t = 0; t < 4; t++) {
            int kq0 = n0 + wx*32 + t*8 + tg*2;
            unsigned kb[2];
#pragma unroll
            for (int cc = 0; cc < 2; cc++) {
                int kq = kq0 + cc;
                int kv = kq / GW_, kh = kq - kv * GW_;
                int dv = kv - qv, dh = kh - qh;
                int ad = (dv < 0 ? -dv : dv) + (dh < 0 ? -dh : dh);
                float pbv = (ad <= 3) ? pbq[(dv + 3) * 7 + (dh + 3)] : pb0;
                float sc = (acc[t][rr*2 + cc] + pbv) * SCALE_;
                unsigned bts = __float_as_uint(sc);
                kb[cc] = (bts & 0x80000000u) ? ~bts : (bts | 0x80000000u);
            }
            *reinterpret_cast<uint2*>(srow + kq0) = make_uint2(kb[0], kb[1]);
        }
    }
}

// ---------------- attn_row: 3-pass (11/11/10-bit) radix select + softmax + sparse P.V ----------------
__global__ void __launch_bounds__(256) attn_row_kernel() {
    int bx = blockIdx.x;                 // h*S + q
    int h = bx / S_, q = bx - h * S_;
    const unsigned* srow = g_skey + (size_t)bx * S_;
    __shared__ unsigned hist[2048];
    __shared__ unsigned sufw[8];
    __shared__ int   sidx[256];
    __shared__ float sval[256];
    __shared__ float pvred[4][DH_];
    __shared__ unsigned smaxw[8];
    __shared__ float ssum[8];
    __shared__ int sh_b, sh_k, sh_k2, sh_cnt;
    __shared__ float sh_inv;
    __shared__ unsigned sh_maxu;
    int tid = threadIdx.x;
    int wid = tid >> 5, lane = tid & 31;

    unsigned key[7];
    int nkk = (tid < 64) ? 7 : 6;
#pragma unroll
    for (int j = 0; j < 6; j++) key[j] = srow[tid + j*256];
    key[6] = (tid < 64) ? srow[tid + 1536] : 0u;

    unsigned mxu = 0u;
#pragma unroll
    for (int j = 0; j < 7; j++) mxu = max(mxu, key[j]);
    for (int o = 16; o; o >>= 1) mxu = max(mxu, __shfl_xor_sync(0xffffffffu, mxu, o));
    if (lane == 0) smaxw[wid] = mxu;
    if (tid == 0) { sh_k = TOPK_; sh_cnt = 0; }
    __syncthreads();
    if (tid == 0) {
        unsigned m = smaxw[0];
#pragma unroll
        for (int w = 1; w < 8; w++) m = max(m, smaxw[w]);
        sh_maxu = m;
    }

    unsigned pref = 0u;   // accumulated high bits (left-aligned as we go)
    // pass p=0: bits [31:21] (shift 21, 11 bits); p=1: bits [20:10]; p=2: bits [9:0]
#pragma unroll
    for (int p = 0; p < 3; p++) {
#pragma unroll
        for (int z = 0; z < 8; z++) hist[tid + z*256] = 0u;
        __syncthreads();
        for (int j = 0; j < nkk; j++) {
            unsigned u = key[j];
            unsigned b;
            bool ok;
            if (p == 0)      { ok = true;                       b = u >> 21; }
            else if (p == 1) { ok = ((u >> 21) == pref);        b = (u >> 10) & 2047u; }
            else             { ok = ((u >> 10) == pref);        b = u & 1023u; }
            if (ok) {
                unsigned act = __activemask();
                unsigned mmask = __match_any_sync(act, b);
                int leader = __ffs(mmask) - 1;
                if (lane == leader) atomicAdd(&hist[b], (unsigned)__popc(mmask));
            }
        }
        __syncthreads();
        // parallel suffix select over 2048 bins (8 bins/thread, ascending)
        unsigned c[8];
        unsigned local = 0;
#pragma unroll
        for (int i = 0; i < 8; i++) { c[i] = hist[tid*8 + i]; local += c[i]; }
        unsigned s = local;
#pragma unroll
        for (int o = 1; o < 32; o <<= 1) {
            unsigned t = __shfl_down_sync(0xffffffffu, s, o);
            if (lane + o < 32) s += t;
        }
        if (lane == 0) sufw[wid] = s;
        __syncthreads();
        unsigned add = 0;
        for (int w = wid + 1; w < 8; w++) add += sufw[w];
        unsigned ge_chunk = s + add;        // keys in bins >= tid*8
        unsigned kkr = (unsigned)sh_k;
        unsigned pre = 0;
#pragma unroll
        for (int i = 0; i < 8; i++) {
            unsigned incl = ge_chunk - pre;
            unsigned excl = incl - c[i];
            if (incl >= kkr && excl < kkr) { sh_b = tid*8 + i; sh_k2 = (int)(kkr - excl); }
            pre += c[i];
        }
        __syncthreads();
        unsigned bd = (unsigned)sh_b;
        if (p == 0)      pref = bd;                 // 11 bits
        else if (p == 1) pref = (pref << 11) | bd;  // 22 bits
        else             pref = (pref << 10) | bd;  // 32 bits
        if (tid == 0) sh_k = sh_k2;
        __syncthreads();
    }
    unsigned thr = pref;
    unsigned mu = sh_maxu;
    float mxv = (mu & 0x80000000u) ? __uint_as_float(mu ^ 0x80000000u) : __uint_as_float(~mu);

    for (int j = 0; j < nkk; j++) {
        unsigned u = key[j];
        if (u >= thr) {
            int p = atomicAdd(&sh_cnt, 1);
            if (p < 256) {
                float v = (u & 0x80000000u) ? __uint_as_float(u ^ 0x80000000u)
                                            : __uint_as_float(~u);
                sidx[p] = tid + j*256;
                sval[p] = expf(v - mxv);
            }
        }
    }
    __syncthreads();
    int cnt = min(sh_cnt, 256);

    {
        float s = 0.f;
        for (int i = tid; i < cnt; i += 256) s += sval[i];
        for (int o = 16; o; o >>= 1) s += __shfl_xor_sync(0xffffffffu, s, o);
        if (lane == 0) ssum[wid] = s;
        __syncthreads();
        if (tid == 0) {
            float t = ssum[0];
#pragma unroll
            for (int w = 1; w < 8; w++) t += ssum[w];
            sh_inv = 1.f / t;
        }
        __syncthreads();
    }

    {
        int g = tid >> 6, d = tid & 63;
        const float* V = g_v + (size_t)h * S_ * DH_;
        float acc = 0.f;
        for (int i = g; i < cnt; i += 4) acc = fmaf(sval[i], V[sidx[i] * DH_ + d], acc);
        pvred[g][d] = acc;
        __syncthreads();
        if (tid < DH_) {
            float r = pvred[0][tid] + pvred[1][tid] + pvred[2][tid] + pvred[3][tid];
            g_att[q * INNER_ + h * DH_ + tid] = r * sh_inv;
        }
    }
}

// ---------------- host launcher ----------------
extern "C" void kernel_launch(void* const* d_in, const int* in_sizes, int n_in,
                              void* d_out, int out_size) {
    (void)in_sizes; (void)n_in; (void)out_size;
    const float* x    = (const float*)d_in[0];
    const float* Wqkv = (const float*)d_in[1];
    const float* Wo   = (const float*)d_in[2];
    const float* ln1g = (const float*)d_in[3];
    const float* ln1b = (const float*)d_in[4];
    const float* ln2g = (const float*)d_in[5];
    const float* ln2b = (const float*)d_in[6];
    const float* relb = (const float*)d_in[7];
    const float* w1   = (const float*)d_in[8];
    const float* b1   = (const float*)d_in[9];
    const float* w2   = (const float*)d_in[10];
    const float* b2   = (const float*)d_in[11];

    init_h_kernel<<<(S_*DIM_ + 255) / 256, 256>>>(x);
    rbT_kernel<<<16, 256>>>(relb);

    for (int l = 0; l < NL_; l++) {
        if (l == 0) ln_kernel<<<S_, 128>>>(ln1g, ln1b);
        else        ln_sum3<<<S_, 128>>>(ln1g + l*DIM_, ln1b + l*DIM_);   // consumes FF2 partials
        gemm64db<0><<<dim3(18, 25), 256>>>(Wqkv + (size_t)l*DIM_*3*INNER_, nullptr, 3*INNER_, DIM_);
        pb_gemm<<<dim3(1, (NH_*S_)/64), 256>>>();
        scores_mma<<<dim3(25, 25, NH_), 256>>>();
        attn_row_kernel<<<NH_*S_, 256>>>();
        gemm64db<1><<<dim3(6, 25, 3), 256>>>(Wo + (size_t)l*INNER_*DIM_, nullptr, DIM_, INNER_/3);
        ln_sum3<<<S_, 128>>>(ln2g + l*DIM_, ln2b + l*DIM_);               // consumes Wo partials
        gemm64db<2><<<dim3(24, 25), 256>>>(w1 + (size_t)l*DIM_*HID_, b1 + l*HID_, HID_, DIM_);
        gemm64db<3><<<dim3(6, 25, 3), 256>>>(w2 + (size_t)l*HID_*DIM_, b2 + l*DIM_, DIM_, HID_/3);
    }

    write_out_sum<<<(S_*DIM_ + 255) / 256, 256>>>((float*)d_out);
}

// round 11
// speedup vs baseline: 1.0914x; 1.0914x over previous
#include <cuda_runtime.h>
#include <float.h>

#define S_    1600
#define DIM_  384
#define NH_   6
#define DH_   64
#define INNER_ 384
#define HID_  1536
#define NL_   6
#define GW_   40
#define TOPK_ 32
#define SCALE_ 0.05103103630798288f   // 384^-0.5

// ---------------- device scratch ----------------
__device__ float g_h[S_*DIM_];
__device__ float g_n[S_*DIM_];
__device__ float g_q[NH_*S_*DH_];
__device__ float g_k[NH_*S_*DH_];
__device__ float g_v[NH_*S_*DH_];
__device__ float g_pb[NH_*S_*64];
__device__ float g_rbT[64*64];
__device__ unsigned g_skey[(long long)NH_*S_*S_];
__device__ float g_att[S_*INNER_];
__device__ float g_ff1[S_*HID_];

// ---------------- tf32 helpers ----------------
__device__ __forceinline__ unsigned f2tf32(float x) {
    unsigned r;
    asm("cvt.rna.tf32.f32 %0, %1;" : "=r"(r) : "f"(x));
    return r;
}
__device__ __forceinline__ void mma_tf32(float* c, const unsigned* a, const unsigned* b) {
    asm volatile(
        "mma.sync.aligned.m16n8k8.row.col.f32.tf32.tf32.f32 "
        "{%0,%1,%2,%3}, {%4,%5,%6,%7}, {%8,%9}, {%0,%1,%2,%3};"
        : "+f"(c[0]), "+f"(c[1]), "+f"(c[2]), "+f"(c[3])
        : "r"(a[0]), "r"(a[1]), "r"(a[2]), "r"(a[3]), "r"(b[0]), "r"(b[1]));
}
__device__ __forceinline__ uint2 split_tf32(float x) {
    unsigned hi = f2tf32(x);
    unsigned lo = f2tf32(x - __uint_as_float(hi));
    return make_uint2(hi, lo);
}

// ---------------- trivial kernels ----------------
__global__ void init_h_kernel(const float* __restrict__ x) {
    int i = blockIdx.x * blockDim.x + threadIdx.x;
    if (i < S_*DIM_) g_h[i] = x[i];
}
__global__ void write_out_kernel(float* __restrict__ out) {
    int i = blockIdx.x * blockDim.x + threadIdx.x;
    if (i < S_*DIM_) out[i] = g_h[i];
}
__global__ void rbT_kernel(const float* __restrict__ rb) {
    int i = blockIdx.x * blockDim.x + threadIdx.x;
    if (i < 64*64) {
        int d = i >> 6, m = i & 63;
        g_rbT[d*64 + m] = (m < 49) ? rb[m*64 + d] : 0.f;
    }
}

// ---------------- LayerNorm ----------------
__global__ void ln_kernel(const float* __restrict__ gamma, const float* __restrict__ beta) {
    int row = blockIdx.x;
    const float* x = g_h + row * DIM_;
    float s = 0.f, s2 = 0.f;
    for (int i = threadIdx.x; i < DIM_; i += blockDim.x) { float v = x[i]; s += v; s2 += v*v; }
    for (int o = 16; o; o >>= 1) {
        s  += __shfl_xor_sync(0xffffffffu, s,  o);
        s2 += __shfl_xor_sync(0xffffffffu, s2, o);
    }
    __shared__ float rs[4], rs2[4];
    int w = threadIdx.x >> 5;
    if ((threadIdx.x & 31) == 0) { rs[w] = s; rs2[w] = s2; }
    __syncthreads();
    s  = rs[0]  + rs[1]  + rs[2]  + rs[3];
    s2 = rs2[0] + rs2[1] + rs2[2] + rs2[3];
    float mean = s * (1.f / DIM_);
    float var  = s2 * (1.f / DIM_) - mean * mean;
    float inv  = rsqrtf(var + 1e-5f);
    for (int i = threadIdx.x; i < DIM_; i += blockDim.x)
        g_n[row*DIM_ + i] = (x[i] - mean) * inv * gamma[i] + beta[i];
}

// ========== double-buffered 64x64x16 SGEMM, 4x4 register tiles (R9-proven) ==========
template<int MODE>
__global__ void __launch_bounds__(256) gemm64db(const float* __restrict__ B,
                                                const float* __restrict__ bias,
                                                int N, int K) {
    const float* A = (MODE == 0 || MODE == 2) ? g_n : (MODE == 1 ? g_att : g_ff1);
    __shared__ __align__(16) float As[2][16][68];
    __shared__ __align__(16) float Bs[2][16][68];
    int tid = threadIdx.x;
    int tx = tid & 15, ty = tid >> 4;
    int m0 = blockIdx.y * 64, n0 = blockIdx.x * 64;
    int arow = tid >> 2, acol = (tid & 3) * 4;
    int brow = tid >> 4, bcol = (tid & 15) * 4;
    const int nk = K >> 4;
    {
        float4 av = *reinterpret_cast<const float4*>(A + (size_t)(m0 + arow) * K + acol);
        As[0][acol+0][arow] = av.x; As[0][acol+1][arow] = av.y;
        As[0][acol+2][arow] = av.z; As[0][acol+3][arow] = av.w;
        float4 bv = *reinterpret_cast<const float4*>(B + (size_t)brow * N + n0 + bcol);
        *reinterpret_cast<float4*>(&Bs[0][brow][bcol]) = bv;
    }
    __syncthreads();
    float acc[4][4] = {};
    for (int t = 0; t < nk; t++) {
        int cur = t & 1, nxt = cur ^ 1;
        float4 av, bv;
        bool more = (t + 1 < nk);
        if (more) {
            int k0 = (t + 1) << 4;
            av = *reinterpret_cast<const float4*>(A + (size_t)(m0 + arow) * K + k0 + acol);
            bv = *reinterpret_cast<const float4*>(B + (size_t)(k0 + brow) * N + n0 + bcol);
        }
#pragma unroll
        for (int kk = 0; kk < 16; kk++) {
            float4 a4 = *reinterpret_cast<const float4*>(&As[cur][kk][ty*4]);
            float4 b4 = *reinterpret_cast<const float4*>(&Bs[cur][kk][tx*4]);
            float ar[4] = {a4.x, a4.y, a4.z, a4.w};
            float br[4] = {b4.x, b4.y, b4.z, b4.w};
#pragma unroll
            for (int i = 0; i < 4; i++)
#pragma unroll
                for (int j = 0; j < 4; j++)
                    acc[i][j] = fmaf(ar[i], br[j], acc[i][j]);
        }
        if (more) {
            As[nxt][acol+0][arow] = av.x; As[nxt][acol+1][arow] = av.y;
            As[nxt][acol+2][arow] = av.z; As[nxt][acol+3][arow] = av.w;
            *reinterpret_cast<float4*>(&Bs[nxt][brow][bcol]) = bv;
        }
        __syncthreads();
    }
#pragma unroll
    for (int i = 0; i < 4; i++) {
        int m = m0 + ty*4 + i;
#pragma unroll
        for (int j = 0; j < 4; j++) {
            int n = n0 + tx*4 + j;
            float v = acc[i][j];
            if (MODE == 0) {
                int idx = n / 3, r = n - idx * 3;
                int hh = idx >> 6, d = idx & 63;
                float* dst = (r == 0) ? g_q : (r == 1) ? g_k : g_v;
                dst[(hh * S_ + m) * DH_ + d] = v;
            } else if (MODE == 1) {
                g_h[m * DIM_ + n] += v;
            } else if (MODE == 2) {
                float t2 = v + bias[n];
                g_ff1[m * HID_ + n] = t2 > 0.f ? t2 : 0.2f * t2;
            } else {
                g_h[m * DIM_ + n] += v + bias[n];
            }
        }
    }
}

// ---------------- pb GEMM: g_pb[9600x64] = g_q @ g_rbT ----------------
__global__ void __launch_bounds__(256) pb_gemm() {
    const float* A = g_q;
    const float* B = g_rbT;
    __shared__ __align__(16) float As[16][68];
    __shared__ __align__(16) float Bs[16][68];
    int tid = threadIdx.x;
    int tx = tid & 15, ty = tid >> 4;
    int m0 = blockIdx.y * 64;
    int arow = tid >> 2, acol = (tid & 3) * 4;
    int brow = tid >> 4, bcol = (tid & 15) * 4;
    float acc[4][4] = {};
    for (int k0 = 0; k0 < 64; k0 += 16) {
        float4 av = *reinterpret_cast<const float4*>(A + (size_t)(m0 + arow) * 64 + k0 + acol);
        As[acol+0][arow] = av.x; As[acol+1][arow] = av.y;
        As[acol+2][arow] = av.z; As[acol+3][arow] = av.w;
        float4 bv = *reinterpret_cast<const float4*>(B + (size_t)(k0 + brow) * 64 + bcol);
        *reinterpret_cast<float4*>(&Bs[brow][bcol]) = bv;
        __syncthreads();
#pragma unroll
        for (int kk = 0; kk < 16; kk++) {
            float4 a4 = *reinterpret_cast<const float4*>(&As[kk][ty*4]);
            float4 b4 = *reinterpret_cast<const float4*>(&Bs[kk][tx*4]);
            float ar[4] = {a4.x, a4.y, a4.z, a4.w};
            float br[4] = {b4.x, b4.y, b4.z, b4.w};
#pragma unroll
            for (int i = 0; i < 4; i++)
#pragma unroll
                for (int j = 0; j < 4; j++)
                    acc[i][j] = fmaf(ar[i], br[j], acc[i][j]);
        }
        __syncthreads();
    }
#pragma unroll
    for (int i = 0; i < 4; i++)
#pragma unroll
        for (int j = 0; j < 4; j++)
            g_pb[(m0 + ty*4 + i) * 64 + tx*4 + j] = acc[i][j];
}

// ---------------- scores via split-tf32 MMA, hi/lo converted ONCE at staging ----------------
// Two k-chunks of 32 cols: smem holds hi/lo uint2 tiles (34.8 KB static).
__global__ void __launch_bounds__(256) scores_mma() {
    int h = blockIdx.z;
    const float* Q  = g_q + (size_t)h * S_ * DH_;
    const float* Km = g_k + (size_t)h * S_ * DH_;
    __shared__ __align__(16) uint2 Qhl[64][34];
    __shared__ __align__(16) uint2 Khl[64][34];
    int tid = threadIdx.x;
    int m0 = blockIdx.y * 64, n0 = blockIdx.x * 64;

    int wid = tid >> 5, lane = tid & 31;
    int wy = wid >> 1, wx = wid & 1;
    int gr = lane >> 2, tg = lane & 3;

    float acc[4][4] = {};
#pragma unroll
    for (int c = 0; c < 2; c++) {
        // stage chunk: 64 rows x 32 cols per array; convert to hi/lo once
#pragma unroll
        for (int i = 0; i < 2; i++) {
            int e = tid + i * 256;            // 512 float4 slots
            int row = e >> 3, col4 = (e & 7) * 4;
            float4 qv = *reinterpret_cast<const float4*>(Q + (size_t)(m0 + row) * DH_ + c*32 + col4);
            Qhl[row][col4+0] = split_tf32(qv.x);
            Qhl[row][col4+1] = split_tf32(qv.y);
            Qhl[row][col4+2] = split_tf32(qv.z);
            Qhl[row][col4+3] = split_tf32(qv.w);
            float4 kv = *reinterpret_cast<const float4*>(Km + (size_t)(n0 + row) * DH_ + c*32 + col4);
            Khl[row][col4+0] = split_tf32(kv.x);
            Khl[row][col4+1] = split_tf32(kv.y);
            Khl[row][col4+2] = split_tf32(kv.z);
            Khl[row][col4+3] = split_tf32(kv.w);
        }
        __syncthreads();
#pragma unroll
        for (int k0 = 0; k0 < 32; k0 += 8) {
            int ar = wy*16 + gr;
            uint2 q0 = Qhl[ar    ][k0 + tg];
            uint2 q1 = Qhl[ar + 8][k0 + tg];
            uint2 q2 = Qhl[ar    ][k0 + tg + 4];
            uint2 q3 = Qhl[ar + 8][k0 + tg + 4];
            unsigned ah[4] = {q0.x, q1.x, q2.x, q3.x};
            unsigned al[4] = {q0.y, q1.y, q2.y, q3.y};
#pragma unroll
            for (int t = 0; t < 4; t++) {
                int bn = wx*32 + t*8 + gr;
                uint2 b0 = Khl[bn][k0 + tg];
                uint2 b1 = Khl[bn][k0 + tg + 4];
                unsigned bh[2] = {b0.x, b1.x};
                unsigned bl[2] = {b0.y, b1.y};
                mma_tf32(acc[t], ah, bh);
                mma_tf32(acc[t], ah, bl);
                mma_tf32(acc[t], al, bh);
            }
        }
        __syncthreads();
    }

    // epilogue: bias gather + monotone key, uint2 stores
#pragma unroll
    for (int rr = 0; rr < 2; rr++) {
        int q = m0 + wy*16 + gr + rr*8;
        int qv = q / GW_, qh = q - qv * GW_;
        const float* pbq = g_pb + ((size_t)h * S_ + q) * 64;
        float pb0 = pbq[0];
        unsigned* srow = g_skey + ((size_t)h * S_ + q) * S_;
#pragma unroll
        for (int t = 0; t < 4; t++) {
            int kq0 = n0 + wx*32 + t*8 + tg*2;
            unsigned kb[2];
#pragma unroll
            for (int cc = 0; cc < 2; cc++) {
                int kq = kq0 + cc;
                int kv = kq / GW_, kh = kq - kv * GW_;
                int dv = kv - qv, dh = kh - qh;
                int ad = (dv < 0 ? -dv : dv) + (dh < 0 ? -dh : dh);
                float pbv = (ad <= 3) ? pbq[(dv + 3) * 7 + (dh + 3)] : pb0;
                float sc = (acc[t][rr*2 + cc] + pbv) * SCALE_;
                unsigned bts = __float_as_uint(sc);
                kb[cc] = (bts & 0x80000000u) ? ~bts : (bts | 0x80000000u);
            }
            *reinterpret_cast<uint2*>(srow + kq0) = make_uint2(kb[0], kb[1]);
        }
    }
}

// ---------------- attn_row: register keys + warp-aggregated hist + parallel select (R9-proven) ----------------
__global__ void __launch_bounds__(256) attn_row_kernel() {
    int bx = blockIdx.x;                 // h*S + q
    int h = bx / S_, q = bx - h * S_;
    const unsigned* srow = g_skey + (size_t)bx * S_;
    __shared__ unsigned hist[256];
    __shared__ unsigned sufw[8];
    __shared__ int   sidx[256];
    __shared__ float sval[256];
    __shared__ float pvred[4][DH_];
    __shared__ unsigned smaxw[8];
    __shared__ float ssum[8];
    __shared__ int sh_b, sh_k, sh_k2, sh_cnt;
    __shared__ float sh_inv;
    __shared__ unsigned sh_maxu;
    int tid = threadIdx.x;
    int wid = tid >> 5, lane = tid & 31;

    unsigned key[7];
    int nkk = (tid < 64) ? 7 : 6;
#pragma unroll
    for (int j = 0; j < 6; j++) key[j] = srow[tid + j*256];
    key[6] = (tid < 64) ? srow[tid + 1536] : 0u;

    unsigned mxu = 0u;
#pragma unroll
    for (int j = 0; j < 7; j++) mxu = max(mxu, key[j]);
    for (int o = 16; o; o >>= 1) mxu = max(mxu, __shfl_xor_sync(0xffffffffu, mxu, o));
    if (lane == 0) smaxw[wid] = mxu;
    if (tid == 0) { sh_k = TOPK_; sh_cnt = 0; }
    __syncthreads();
    if (tid == 0) {
        unsigned m = smaxw[0];
#pragma unroll
        for (int w = 1; w < 8; w++) m = max(m, smaxw[w]);
        sh_maxu = m;
    }

    unsigned pref = 0u;
    for (int shift = 24; shift >= 0; shift -= 8) {
        hist[tid] = 0u;
        __syncthreads();
        unsigned maskhi = (shift == 24) ? 0u : (0xFFFFFFFFu << (shift + 8));
        for (int j = 0; j < nkk; j++) {
            unsigned u = key[j];
            if ((u & maskhi) == pref) {
                unsigned b = (u >> shift) & 255u;
                unsigned act = __activemask();
                unsigned mmask = __match_any_sync(act, b);
                int leader = __ffs(mmask) - 1;
                if (lane == leader) atomicAdd(&hist[b], (unsigned)__popc(mmask));
            }
        }
        __syncthreads();
        unsigned c = hist[tid];
        unsigned s = c;
#pragma unroll
        for (int o = 1; o < 32; o <<= 1) {
            unsigned t = __shfl_down_sync(0xffffffffu, s, o);
            if (lane + o < 32) s += t;
        }
        if (lane == 0) sufw[wid] = s;
        __syncthreads();
        unsigned add = 0;
        for (int w = wid + 1; w < 8; w++) add += sufw[w];
        unsigned suf_incl = s + add;
        unsigned suf_excl = suf_incl - c;
        unsigned kkr = (unsigned)sh_k;
        if (suf_incl >= kkr && suf_excl < kkr) { sh_b = tid; sh_k2 = (int)(kkr - suf_excl); }
        __syncthreads();
        pref |= ((unsigned)sh_b) << shift;
        if (tid == 0) sh_k = sh_k2;
        __syncthreads();
    }
    unsigned thr = pref;
    unsigned mu = sh_maxu;
    float mxv = (mu & 0x80000000u) ? __uint_as_float(mu ^ 0x80000000u) : __uint_as_float(~mu);

    for (int j = 0; j < nkk; j++) {
        unsigned u = key[j];
        if (u >= thr) {
            int p = atomicAdd(&sh_cnt, 1);
            if (p < 256) {
                float v = (u & 0x80000000u) ? __uint_as_float(u ^ 0x80000000u)
                                            : __uint_as_float(~u);
                sidx[p] = tid + j*256;
                sval[p] = expf(v - mxv);
            }
        }
    }
    __syncthreads();
    int cnt = min(sh_cnt, 256);

    {
        float s = 0.f;
        for (int i = tid; i < cnt; i += 256) s += sval[i];
        for (int o = 16; o; o >>= 1) s += __shfl_xor_sync(0xffffffffu, s, o);
        if (lane == 0) ssum[wid] = s;
        __syncthreads();
        if (tid == 0) {
            float t = ssum[0];
#pragma unroll
            for (int w = 1; w < 8; w++) t += ssum[w];
            sh_inv = 1.f / t;
        }
        __syncthreads();
    }

    {
        int g = tid >> 6, d = tid & 63;
        const float* V = g_v + (size_t)h * S_ * DH_;
        float acc = 0.f;
        for (int i = g; i < cnt; i += 4) acc = fmaf(sval[i], V[sidx[i] * DH_ + d], acc);
        pvred[g][d] = acc;
        __syncthreads();
        if (tid < DH_) {
            float r = pvred[0][tid] + pvred[1][tid] + pvred[2][tid] + pvred[3][tid];
            g_att[q * INNER_ + h * DH_ + tid] = r * sh_inv;
        }
    }
}

// ---------------- host launcher ----------------
extern "C" void kernel_launch(void* const* d_in, const int* in_sizes, int n_in,
                              void* d_out, int out_size) {
    (void)in_sizes; (void)n_in; (void)out_size;
    const float* x    = (const float*)d_in[0];
    const float* Wqkv = (const float*)d_in[1];
    const float* Wo   = (const float*)d_in[2];
    const float* ln1g = (const float*)d_in[3];
    const float* ln1b = (const float*)d_in[4];
    const float* ln2g = (const float*)d_in[5];
    const float* ln2b = (const float*)d_in[6];
    const float* relb = (const float*)d_in[7];
    const float* w1   = (const float*)d_in[8];
    const float* b1   = (const float*)d_in[9];
    const float* w2   = (const float*)d_in[10];
    const float* b2   = (const float*)d_in[11];

    init_h_kernel<<<(S_*DIM_ + 255) / 256, 256>>>(x);
    rbT_kernel<<<16, 256>>>(relb);

    for (int l = 0; l < NL_; l++) {
        ln_kernel<<<S_, 128>>>(ln1g + l*DIM_, ln1b + l*DIM_);
        gemm64db<0><<<dim3(18, 25), 256>>>(Wqkv + (size_t)l*DIM_*3*INNER_, nullptr, 3*INNER_, DIM_);
        pb_gemm<<<dim3(1, (NH_*S_)/64), 256>>>();
        scores_mma<<<dim3(25, 25, NH_), 256>>>();
        attn_row_kernel<<<NH_*S_, 256>>>();
        gemm64db<1><<<dim3(6, 25), 256>>>(Wo + (size_t)l*INNER_*DIM_, nullptr, DIM_, INNER_);
        ln_kernel<<<S_, 128>>>(ln2g + l*DIM_, ln2b + l*DIM_);
        gemm64db<2><<<dim3(24, 25), 256>>>(w1 + (size_t)l*DIM_*HID_, b1 + l*HID_, HID_, DIM_);
        gemm64db<3><<<dim3(6, 25), 256>>>(w2 + (size_t)l*HID_*DIM_, b2 + l*DIM_, DIM_, HID_);
    }

    write_out_kernel<<<(S_*DIM_ + 255) / 256, 256>>>((float*)d_out);
}

// round 12
// speedup vs baseline: 1.1291x; 1.0346x over previous
#include <cuda_runtime.h>
#include <float.h>

#define S_    1600
#define DIM_  384
#define NH_   6
#define DH_   64
#define INNER_ 384
#define HID_  1536
#define NL_   6
#define GW_   40
#define TOPK_ 32
#define SCALE_ 0.05103103630798288f   // 384^-0.5

// ---------------- device scratch ----------------
__device__ float g_h[S_*DIM_];
__device__ float g_n[S_*DIM_];
__device__ float g_q[NH_*S_*DH_];
__device__ float g_k[NH_*S_*DH_];
__device__ float g_v[NH_*S_*DH_];
__device__ float g_pb[NH_*S_*64];
__device__ float g_rbT[64*64];
__device__ unsigned g_skey[(long long)NH_*S_*S_];
__device__ float g_att[S_*INNER_];
__device__ float g_ff1[S_*HID_];

// ---------------- tf32 helpers ----------------
__device__ __forceinline__ unsigned f2tf32(float x) {
    unsigned r;
    asm("cvt.rna.tf32.f32 %0, %1;" : "=r"(r) : "f"(x));
    return r;
}
__device__ __forceinline__ void mma_tf32(float* c, const unsigned* a, const unsigned* b) {
    asm volatile(
        "mma.sync.aligned.m16n8k8.row.col.f32.tf32.tf32.f32 "
        "{%0,%1,%2,%3}, {%4,%5,%6,%7}, {%8,%9}, {%0,%1,%2,%3};"
        : "+f"(c[0]), "+f"(c[1]), "+f"(c[2]), "+f"(c[3])
        : "r"(a[0]), "r"(a[1]), "r"(a[2]), "r"(a[3]), "r"(b[0]), "r"(b[1]));
}

// ---------------- trivial kernels ----------------
__global__ void init_h_kernel(const float* __restrict__ x) {
    int i = blockIdx.x * blockDim.x + threadIdx.x;
    if (i < S_*DIM_) g_h[i] = x[i];
}
__global__ void write_out_kernel(float* __restrict__ out) {
    int i = blockIdx.x * blockDim.x + threadIdx.x;
    if (i < S_*DIM_) out[i] = g_h[i];
}
__global__ void rbT_kernel(const float* __restrict__ rb) {
    int i = blockIdx.x * blockDim.x + threadIdx.x;
    if (i < 64*64) {
        int d = i >> 6, m = i & 63;
        g_rbT[d*64 + m] = (m < 49) ? rb[m*64 + d] : 0.f;
    }
}

// ---------------- LayerNorm ----------------
__global__ void ln_kernel(const float* __restrict__ gamma, const float* __restrict__ beta) {
    int row = blockIdx.x;
    const float* x = g_h + row * DIM_;
    float s = 0.f, s2 = 0.f;
    for (int i = threadIdx.x; i < DIM_; i += blockDim.x) { float v = x[i]; s += v; s2 += v*v; }
    for (int o = 16; o; o >>= 1) {
        s  += __shfl_xor_sync(0xffffffffu, s,  o);
        s2 += __shfl_xor_sync(0xffffffffu, s2, o);
    }
    __shared__ float rs[4], rs2[4];
    int w = threadIdx.x >> 5;
    if ((threadIdx.x & 31) == 0) { rs[w] = s; rs2[w] = s2; }
    __syncthreads();
    s  = rs[0]  + rs[1]  + rs[2]  + rs[3];
    s2 = rs2[0] + rs2[1] + rs2[2] + rs2[3];
    float mean = s * (1.f / DIM_);
    float var  = s2 * (1.f / DIM_) - mean * mean;
    float inv  = rsqrtf(var + 1e-5f);
    for (int i = threadIdx.x; i < DIM_; i += blockDim.x)
        g_n[row*DIM_ + i] = (x[i] - mean) * inv * gamma[i] + beta[i];
}

// ========== double-buffered 64x64x16 SGEMM, 4x4 register tiles (R9-proven) ==========
template<int MODE>
__global__ void __launch_bounds__(256) gemm64db(const float* __restrict__ B,
                                                const float* __restrict__ bias,
                                                int N, int K) {
    const float* A = (MODE == 0 || MODE == 2) ? g_n : (MODE == 1 ? g_att : g_ff1);
    __shared__ __align__(16) float As[2][16][68];
    __shared__ __align__(16) float Bs[2][16][68];
    int tid = threadIdx.x;
    int tx = tid & 15, ty = tid >> 4;
    int m0 = blockIdx.y * 64, n0 = blockIdx.x * 64;
    int arow = tid >> 2, acol = (tid & 3) * 4;
    int brow = tid >> 4, bcol = (tid & 15) * 4;
    const int nk = K >> 4;
    {
        float4 av = *reinterpret_cast<const float4*>(A + (size_t)(m0 + arow) * K + acol);
        As[0][acol+0][arow] = av.x; As[0][acol+1][arow] = av.y;
        As[0][acol+2][arow] = av.z; As[0][acol+3][arow] = av.w;
        float4 bv = *reinterpret_cast<const float4*>(B + (size_t)brow * N + n0 + bcol);
        *reinterpret_cast<float4*>(&Bs[0][brow][bcol]) = bv;
    }
    __syncthreads();
    float acc[4][4] = {};
    for (int t = 0; t < nk; t++) {
        int cur = t & 1, nxt = cur ^ 1;
        float4 av, bv;
        bool more = (t + 1 < nk);
        if (more) {
            int k0 = (t + 1) << 4;
            av = *reinterpret_cast<const float4*>(A + (size_t)(m0 + arow) * K + k0 + acol);
            bv = *reinterpret_cast<const float4*>(B + (size_t)(k0 + brow) * N + n0 + bcol);
        }
#pragma unroll
        for (int kk = 0; kk < 16; kk++) {
            float4 a4 = *reinterpret_cast<const float4*>(&As[cur][kk][ty*4]);
            float4 b4 = *reinterpret_cast<const float4*>(&Bs[cur][kk][tx*4]);
            float ar[4] = {a4.x, a4.y, a4.z, a4.w};
            float br[4] = {b4.x, b4.y, b4.z, b4.w};
#pragma unroll
            for (int i = 0; i < 4; i++)
#pragma unroll
                for (int j = 0; j < 4; j++)
                    acc[i][j] = fmaf(ar[i], br[j], acc[i][j]);
        }
        if (more) {
            As[nxt][acol+0][arow] = av.x; As[nxt][acol+1][arow] = av.y;
            As[nxt][acol+2][arow] = av.z; As[nxt][acol+3][arow] = av.w;
            *reinterpret_cast<float4*>(&Bs[nxt][brow][bcol]) = bv;
        }
        __syncthreads();
    }
#pragma unroll
    for (int i = 0; i < 4; i++) {
        int m = m0 + ty*4 + i;
#pragma unroll
        for (int j = 0; j < 4; j++) {
            int n = n0 + tx*4 + j;
            float v = acc[i][j];
            if (MODE == 0) {
                int idx = n / 3, r = n - idx * 3;
                int hh = idx >> 6, d = idx & 63;
                float* dst = (r == 0) ? g_q : (r == 1) ? g_k : g_v;
                dst[(hh * S_ + m) * DH_ + d] = v;
            } else if (MODE == 1) {
                g_h[m * DIM_ + n] += v;
            } else if (MODE == 2) {
                float t2 = v + bias[n];
                g_ff1[m * HID_ + n] = t2 > 0.f ? t2 : 0.2f * t2;
            } else {
                g_h[m * DIM_ + n] += v + bias[n];
            }
        }
    }
}

// ---------------- pb GEMM: g_pb[9600x64] = g_q @ g_rbT ----------------
__global__ void __launch_bounds__(256) pb_gemm() {
    const float* A = g_q;
    const float* B = g_rbT;
    __shared__ __align__(16) float As[16][68];
    __shared__ __align__(16) float Bs[16][68];
    int tid = threadIdx.x;
    int tx = tid & 15, ty = tid >> 4;
    int m0 = blockIdx.y * 64;
    int arow = tid >> 2, acol = (tid & 3) * 4;
    int brow = tid >> 4, bcol = (tid & 15) * 4;
    float acc[4][4] = {};
    for (int k0 = 0; k0 < 64; k0 += 16) {
        float4 av = *reinterpret_cast<const float4*>(A + (size_t)(m0 + arow) * 64 + k0 + acol);
        As[acol+0][arow] = av.x; As[acol+1][arow] = av.y;
        As[acol+2][arow] = av.z; As[acol+3][arow] = av.w;
        float4 bv = *reinterpret_cast<const float4*>(B + (size_t)(k0 + brow) * 64 + bcol);
        *reinterpret_cast<float4*>(&Bs[brow][bcol]) = bv;
        __syncthreads();
#pragma unroll
        for (int kk = 0; kk < 16; kk++) {
            float4 a4 = *reinterpret_cast<const float4*>(&As[kk][ty*4]);
            float4 b4 = *reinterpret_cast<const float4*>(&Bs[kk][tx*4]);
            float ar[4] = {a4.x, a4.y, a4.z, a4.w};
            float br[4] = {b4.x, b4.y, b4.z, b4.w};
#pragma unroll
            for (int i = 0; i < 4; i++)
#pragma unroll
                for (int j = 0; j < 4; j++)
                    acc[i][j] = fmaf(ar[i], br[j], acc[i][j]);
        }
        __syncthreads();
    }
#pragma unroll
    for (int i = 0; i < 4; i++)
#pragma unroll
        for (int j = 0; j < 4; j++)
            g_pb[(m0 + ty*4 + i) * 64 + tx*4 + j] = acc[i][j];
}

// ---------------- scores via split-tf32 MMA (R9-proven) ----------------
__global__ void __launch_bounds__(256) scores_mma() {
    int h = blockIdx.z;
    const float* Q  = g_q + (size_t)h * S_ * DH_;
    const float* Km = g_k + (size_t)h * S_ * DH_;
    __shared__ __align__(16) float Qs[64][68];
    __shared__ __align__(16) float Ks[64][68];
    int tid = threadIdx.x;
    int m0 = blockIdx.y * 64, n0 = blockIdx.x * 64;
#pragma unroll
    for (int i = 0; i < 4; i++) {
        int e = tid + i * 256;
        int row = e >> 4, c = (e & 15) * 4;
        *reinterpret_cast<float4*>(&Qs[row][c]) =
            *reinterpret_cast<const float4*>(Q + (size_t)(m0 + row) * DH_ + c);
        *reinterpret_cast<float4*>(&Ks[row][c]) =
            *reinterpret_cast<const float4*>(Km + (size_t)(n0 + row) * DH_ + c);
    }
    __syncthreads();

    int wid = tid >> 5, lane = tid & 31;
    int wy = wid >> 1, wx = wid & 1;
    int gr = lane >> 2, tg = lane & 3;

    float acc[4][4] = {};
#pragma unroll
    for (int k0 = 0; k0 < 64; k0 += 8) {
        int ar = wy*16 + gr;
        float a[4];
        a[0] = Qs[ar    ][k0 + tg];
        a[1] = Qs[ar + 8][k0 + tg];
        a[2] = Qs[ar    ][k0 + tg + 4];
        a[3] = Qs[ar + 8][k0 + tg + 4];
        unsigned ah[4], al[4];
#pragma unroll
        for (int i = 0; i < 4; i++) {
            ah[i] = f2tf32(a[i]);
            al[i] = f2tf32(a[i] - __uint_as_float(ah[i]));
        }
#pragma unroll
        for (int t = 0; t < 4; t++) {
            int bn = wx*32 + t*8 + gr;
            float b0 = Ks[bn][k0 + tg];
            float b1 = Ks[bn][k0 + tg + 4];
            unsigned bh[2], bl[2];
            bh[0] = f2tf32(b0); bl[0] = f2tf32(b0 - __uint_as_float(bh[0]));
            bh[1] = f2tf32(b1); bl[1] = f2tf32(b1 - __uint_as_float(bh[1]));
            mma_tf32(acc[t], ah, bh);
            mma_tf32(acc[t], ah, bl);
            mma_tf32(acc[t], al, bh);
        }
    }
#pragma unroll
    for (int rr = 0; rr < 2; rr++) {
        int q = m0 + wy*16 + gr + rr*8;
        int qv = q / GW_, qh = q - qv * GW_;
        const float* pbq = g_pb + ((size_t)h * S_ + q) * 64;
        float pb0 = pbq[0];
        unsigned* srow = g_skey + ((size_t)h * S_ + q) * S_;
#pragma unroll
        for (int t = 0; t < 4; t++) {
            int kq0 = n0 + wx*32 + t*8 + tg*2;
            unsigned kb[2];
#pragma unroll
            for (int cc = 0; cc < 2; cc++) {
                int kq = kq0 + cc;
                int kv = kq / GW_, kh = kq - kv * GW_;
                int dv = kv - qv, dh = kh - qh;
                int ad = (dv < 0 ? -dv : dv) + (dh < 0 ? -dh : dh);
                float pbv = (ad <= 3) ? pbq[(dv + 3) * 7 + (dh + 3)] : pb0;
                float sc = (acc[t][rr*2 + cc] + pbv) * SCALE_;
                unsigned bts = __float_as_uint(sc);
                kb[cc] = (bts & 0x80000000u) ? ~bts : (bts | 0x80000000u);
            }
            *reinterpret_cast<uint2*>(srow + kq0) = make_uint2(kb[0], kb[1]);
        }
    }
}

// ---------------- attn_row: register keys + radix select + smem-staged sparse P.V ----------------
__global__ void __launch_bounds__(256) attn_row_kernel() {
    int bx = blockIdx.x;                 // h*S + q
    int h = bx / S_, q = bx - h * S_;
    const unsigned* srow = g_skey + (size_t)bx * S_;
    __shared__ unsigned hist[256];
    __shared__ unsigned sufw[8];
    __shared__ int   sidx[256];
    __shared__ float sval[256];
    __shared__ float sV[64*DH_];         // staged pre-scaled V rows (16 KB)
    __shared__ float pvred[4][DH_];
    __shared__ unsigned smaxw[8];
    __shared__ float ssum[8];
    __shared__ int sh_b, sh_k, sh_k2, sh_cnt;
    __shared__ float sh_inv;
    __shared__ unsigned sh_maxu;
    int tid = threadIdx.x;
    int wid = tid >> 5, lane = tid & 31;

    unsigned key[7];
    int nkk = (tid < 64) ? 7 : 6;
#pragma unroll
    for (int j = 0; j < 6; j++) key[j] = srow[tid + j*256];
    key[6] = (tid < 64) ? srow[tid + 1536] : 0u;

    unsigned mxu = 0u;
#pragma unroll
    for (int j = 0; j < 7; j++) mxu = max(mxu, key[j]);
    for (int o = 16; o; o >>= 1) mxu = max(mxu, __shfl_xor_sync(0xffffffffu, mxu, o));
    if (lane == 0) smaxw[wid] = mxu;
    if (tid == 0) { sh_k = TOPK_; sh_cnt = 0; }
    __syncthreads();
    if (tid == 0) {
        unsigned m = smaxw[0];
#pragma unroll
        for (int w = 1; w < 8; w++) m = max(m, smaxw[w]);
        sh_maxu = m;
    }

    unsigned pref = 0u;
    for (int shift = 24; shift >= 0; shift -= 8) {
        hist[tid] = 0u;
        __syncthreads();
        unsigned maskhi = (shift == 24) ? 0u : (0xFFFFFFFFu << (shift + 8));
        for (int j = 0; j < nkk; j++) {
            unsigned u = key[j];
            if ((u & maskhi) == pref) {
                unsigned b = (u >> shift) & 255u;
                unsigned act = __activemask();
                unsigned mmask = __match_any_sync(act, b);
                int leader = __ffs(mmask) - 1;
                if (lane == leader) atomicAdd(&hist[b], (unsigned)__popc(mmask));
            }
        }
        __syncthreads();
        unsigned c = hist[tid];
        unsigned s = c;
#pragma unroll
        for (int o = 1; o < 32; o <<= 1) {
            unsigned t = __shfl_down_sync(0xffffffffu, s, o);
            if (lane + o < 32) s += t;
        }
        if (lane == 0) sufw[wid] = s;
        __syncthreads();
        unsigned add = 0;
        for (int w = wid + 1; w < 8; w++) add += sufw[w];
        unsigned suf_incl = s + add;
        unsigned suf_excl = suf_incl - c;
        unsigned kkr = (unsigned)sh_k;
        if (suf_incl >= kkr && suf_excl < kkr) { sh_b = tid; sh_k2 = (int)(kkr - suf_excl); }
        __syncthreads();
        pref |= ((unsigned)sh_b) << shift;
        if (tid == 0) sh_k = sh_k2;
        __syncthreads();
    }
    unsigned thr = pref;
    unsigned mu = sh_maxu;
    float mxv = (mu & 0x80000000u) ? __uint_as_float(mu ^ 0x80000000u) : __uint_as_float(~mu);

    // gather survivors + exp (score recovered from key)
    for (int j = 0; j < nkk; j++) {
        unsigned u = key[j];
        if (u >= thr) {
            int p = atomicAdd(&sh_cnt, 1);
            if (p < 256) {
                float v = (u & 0x80000000u) ? __uint_as_float(u ^ 0x80000000u)
                                            : __uint_as_float(~u);
                sidx[p] = tid + j*256;
                sval[p] = expf(v - mxv);
            }
        }
    }
    __syncthreads();
    int cnt = min(sh_cnt, 256);
    int cstage = min(cnt, 64);
    const float* V = g_v + (size_t)h * S_ * DH_;

    // stage pre-scaled V rows into smem (independent LDGs, one L2 round-trip),
    // and concurrently compute the exp-sum.
    for (int idx = tid; idx < cstage * DH_; idx += 256) {
        int i = idx >> 6, d = idx & 63;
        sV[idx] = sval[i] * V[sidx[i] * DH_ + d];
    }
    {
        float s = 0.f;
        for (int i = tid; i < cnt; i += 256) s += sval[i];
        for (int o = 16; o; o >>= 1) s += __shfl_xor_sync(0xffffffffu, s, o);
        if (lane == 0) ssum[wid] = s;
    }
    __syncthreads();
    if (tid == 0) {
        float t = ssum[0];
#pragma unroll
        for (int w = 1; w < 8; w++) t += ssum[w];
        sh_inv = 1.f / t;
    }
    __syncthreads();

    // reduce staged rows (4-way split over i), fallback direct loop if cnt > 64 (tie overflow)
    {
        int g = tid >> 6, d = tid & 63;
        float acc = 0.f;
        for (int i = g; i < cstage; i += 4) acc += sV[i * DH_ + d];
        for (int i = 64 + g; i < cnt; i += 4) acc = fmaf(sval[i], V[sidx[i] * DH_ + d], acc);
        pvred[g][d] = acc;
        __syncthreads();
        if (tid < DH_) {
            float r = pvred[0][tid] + pvred[1][tid] + pvred[2][tid] + pvred[3][tid];
            g_att[q * INNER_ + h * DH_ + tid] = r * sh_inv;
        }
    }
}

// ---------------- host launcher ----------------
extern "C" void kernel_launch(void* const* d_in, const int* in_sizes, int n_in,
                              void* d_out, int out_size) {
    (void)in_sizes; (void)n_in; (void)out_size;
    const float* x    = (const float*)d_in[0];
    const float* Wqkv = (const float*)d_in[1];
    const float* Wo   = (const float*)d_in[2];
    const float* ln1g = (const float*)d_in[3];
    const float* ln1b = (const float*)d_in[4];
    const float* ln2g = (const float*)d_in[5];
    const float* ln2b = (const float*)d_in[6];
    const float* relb = (const float*)d_in[7];
    const float* w1   = (const float*)d_in[8];
    const float* b1   = (const float*)d_in[9];
    const float* w2   = (const float*)d_in[10];
    const float* b2   = (const float*)d_in[11];

    init_h_kernel<<<(S_*DIM_ + 255) / 256, 256>>>(x);
    rbT_kernel<<<16, 256>>>(relb);

    for (int l = 0; l < NL_; l++) {
        ln_kernel<<<S_, 128>>>(ln1g + l*DIM_, ln1b + l*DIM_);
        gemm64db<0><<<dim3(18, 25), 256>>>(Wqkv + (size_t)l*DIM_*3*INNER_, nullptr, 3*INNER_, DIM_);
        pb_gemm<<<dim3(1, (NH_*S_)/64), 256>>>();
        scores_mma<<<dim3(25, 25, NH_), 256>>>();
        attn_row_kernel<<<NH_*S_, 256>>>();
        gemm64db<1><<<dim3(6, 25), 256>>>(Wo + (size_t)l*INNER_*DIM_, nullptr, DIM_, INNER_);
        ln_kernel<<<S_, 128>>>(ln2g + l*DIM_, ln2b + l*DIM_);
        gemm64db<2><<<dim3(24, 25), 256>>>(w1 + (size_t)l*DIM_*HID_, b1 + l*HID_, HID_, DIM_);
        gemm64db<3><<<dim3(6, 25), 256>>>(w2 + (size_t)l*HID_*DIM_, b2 + l*DIM_, DIM_, HID_);
    }

    write_out_kernel<<<(S_*DIM_ + 255) / 256, 256>>>((float*)d_out);
}

// round 13
// speedup vs baseline: 1.1560x; 1.0238x over previous
#include <cuda_runtime.h>
#include <float.h>

#define S_    1600
#define DIM_  384
#define NH_   6
#define DH_   64
#define INNER_ 384
#define HID_  1536
#define NL_   6
#define GW_   40
#define TOPK_ 32
#define SCALE_ 0.05103103630798288f   // 384^-0.5

// ---------------- device scratch ----------------
__device__ float g_h[S_*DIM_];
__device__ float g_n[S_*DIM_];
__device__ float g_q[NH_*S_*DH_];
__device__ float g_k[NH_*S_*DH_];
__device__ float g_v[NH_*S_*DH_];
__device__ float g_pb[NH_*S_*64];
__device__ float g_rbT[64*64];
__device__ unsigned g_skey[(long long)NH_*S_*S_];
__device__ float g_att[S_*INNER_];
__device__ float g_ff1[S_*HID_];

// ---------------- tf32 helpers ----------------
__device__ __forceinline__ unsigned f2tf32(float x) {
    unsigned r;
    asm("cvt.rna.tf32.f32 %0, %1;" : "=r"(r) : "f"(x));
    return r;
}
__device__ __forceinline__ void mma_tf32(float* c, const unsigned* a, const unsigned* b) {
    asm volatile(
        "mma.sync.aligned.m16n8k8.row.col.f32.tf32.tf32.f32 "
        "{%0,%1,%2,%3}, {%4,%5,%6,%7}, {%8,%9}, {%0,%1,%2,%3};"
        : "+f"(c[0]), "+f"(c[1]), "+f"(c[2]), "+f"(c[3])
        : "r"(a[0]), "r"(a[1]), "r"(a[2]), "r"(a[3]), "r"(b[0]), "r"(b[1]));
}

// ---------------- trivial kernels ----------------
__global__ void init_h_kernel(const float* __restrict__ x) {
    int i = blockIdx.x * blockDim.x + threadIdx.x;
    if (i < S_*DIM_) g_h[i] = x[i];
}
__global__ void write_out_kernel(float* __restrict__ out) {
    int i = blockIdx.x * blockDim.x + threadIdx.x;
    if (i < S_*DIM_) out[i] = g_h[i];
}
__global__ void rbT_kernel(const float* __restrict__ rb) {
    int i = blockIdx.x * blockDim.x + threadIdx.x;
    if (i < 64*64) {
        int d = i >> 6, m = i & 63;
        g_rbT[d*64 + m] = (m < 49) ? rb[m*64 + d] : 0.f;
    }
}

// ---------------- LayerNorm ----------------
__global__ void ln_kernel(const float* __restrict__ gamma, const float* __restrict__ beta) {
    int row = blockIdx.x;
    const float* x = g_h + row * DIM_;
    float s = 0.f, s2 = 0.f;
    for (int i = threadIdx.x; i < DIM_; i += blockDim.x) { float v = x[i]; s += v; s2 += v*v; }
    for (int o = 16; o; o >>= 1) {
        s  += __shfl_xor_sync(0xffffffffu, s,  o);
        s2 += __shfl_xor_sync(0xffffffffu, s2, o);
    }
    __shared__ float rs[4], rs2[4];
    int w = threadIdx.x >> 5;
    if ((threadIdx.x & 31) == 0) { rs[w] = s; rs2[w] = s2; }
    __syncthreads();
    s  = rs[0]  + rs[1]  + rs[2]  + rs[3];
    s2 = rs2[0] + rs2[1] + rs2[2] + rs2[3];
    float mean = s * (1.f / DIM_);
    float var  = s2 * (1.f / DIM_) - mean * mean;
    float inv  = rsqrtf(var + 1e-5f);
    for (int i = threadIdx.x; i < DIM_; i += blockDim.x)
        g_n[row*DIM_ + i] = (x[i] - mean) * inv * gamma[i] + beta[i];
}

// ========== double-buffered 64x64x16 SGEMM, 128 threads, 8x4 register tiles ==========
// MODE 0: A=g_n,   QKV scatter -> g_q/g_k/g_v
// MODE 1: A=g_att, g_h += acc
// MODE 2: A=g_n,   g_ff1 = leaky_relu(acc+bias, 0.2)
// MODE 3: A=g_ff1, g_h += acc + bias
template<int MODE>
__global__ void __launch_bounds__(128) gemm64db(const float* __restrict__ B,
                                                const float* __restrict__ bias,
                                                int N, int K) {
    const float* A = (MODE == 0 || MODE == 2) ? g_n : (MODE == 1 ? g_att : g_ff1);
    __shared__ __align__(16) float As[2][16][68];
    __shared__ __align__(16) float Bs[2][16][68];
    int tid = threadIdx.x;
    int tx = tid & 15, ty = tid >> 4;          // tx: 0..15 (n), ty: 0..7 (m)
    int m0 = blockIdx.y * 64, n0 = blockIdx.x * 64;
    // loaders: 2 float4 per array per k-tile
    int ar0 = tid >> 1, ac0 = (tid & 1) * 8;   // A: row 0..63, col 0 or 8 (two float4 below)
    int br0 = tid >> 3, bc0 = (tid & 7) * 8;   // B: krow 0..15, col 0/8...
    const int nk = K >> 4;

    // preload tile 0
    {
        float4 a0 = *reinterpret_cast<const float4*>(A + (size_t)(m0 + ar0) * K + ac0);
        float4 a1 = *reinterpret_cast<const float4*>(A + (size_t)(m0 + ar0) * K + ac0 + 4);
        As[0][ac0+0][ar0] = a0.x; As[0][ac0+1][ar0] = a0.y;
        As[0][ac0+2][ar0] = a0.z; As[0][ac0+3][ar0] = a0.w;
        As[0][ac0+4][ar0] = a1.x; As[0][ac0+5][ar0] = a1.y;
        As[0][ac0+6][ar0] = a1.z; As[0][ac0+7][ar0] = a1.w;
        float4 b0 = *reinterpret_cast<const float4*>(B + (size_t)br0 * N + n0 + bc0);
        float4 b1 = *reinterpret_cast<const float4*>(B + (size_t)br0 * N + n0 + bc0 + 4);
        *reinterpret_cast<float4*>(&Bs[0][br0][bc0]) = b0;
        *reinterpret_cast<float4*>(&Bs[0][br0][bc0+4]) = b1;
    }
    __syncthreads();

    float acc[8][4] = {};
    for (int t = 0; t < nk; t++) {
        int cur = t & 1, nxt = cur ^ 1;
        float4 a0, a1, b0, b1;
        bool more = (t + 1 < nk);
        if (more) {
            int k0 = (t + 1) << 4;
            a0 = *reinterpret_cast<const float4*>(A + (size_t)(m0 + ar0) * K + k0 + ac0);
            a1 = *reinterpret_cast<const float4*>(A + (size_t)(m0 + ar0) * K + k0 + ac0 + 4);
            b0 = *reinterpret_cast<const float4*>(B + (size_t)(k0 + br0) * N + n0 + bc0);
            b1 = *reinterpret_cast<const float4*>(B + (size_t)(k0 + br0) * N + n0 + bc0 + 4);
        }
#pragma unroll
        for (int kk = 0; kk < 16; kk++) {
            float4 x0 = *reinterpret_cast<const float4*>(&As[cur][kk][ty*8]);
            float4 x1 = *reinterpret_cast<const float4*>(&As[cur][kk][ty*8+4]);
            float4 y0 = *reinterpret_cast<const float4*>(&Bs[cur][kk][tx*4]);
            float ar[8] = {x0.x, x0.y, x0.z, x0.w, x1.x, x1.y, x1.z, x1.w};
            float br[4] = {y0.x, y0.y, y0.z, y0.w};
#pragma unroll
            for (int i = 0; i < 8; i++)
#pragma unroll
                for (int j = 0; j < 4; j++)
                    acc[i][j] = fmaf(ar[i], br[j], acc[i][j]);
        }
        if (more) {
            As[nxt][ac0+0][ar0] = a0.x; As[nxt][ac0+1][ar0] = a0.y;
            As[nxt][ac0+2][ar0] = a0.z; As[nxt][ac0+3][ar0] = a0.w;
            As[nxt][ac0+4][ar0] = a1.x; As[nxt][ac0+5][ar0] = a1.y;
            As[nxt][ac0+6][ar0] = a1.z; As[nxt][ac0+7][ar0] = a1.w;
            *reinterpret_cast<float4*>(&Bs[nxt][br0][bc0]) = b0;
            *reinterpret_cast<float4*>(&Bs[nxt][br0][bc0+4]) = b1;
        }
        __syncthreads();
    }

#pragma unroll
    for (int i = 0; i < 8; i++) {
        int m = m0 + ty*8 + i;
#pragma unroll
        for (int j = 0; j < 4; j++) {
            int n = n0 + tx*4 + j;
            float v = acc[i][j];
            if (MODE == 0) {
                int idx = n / 3, r = n - idx * 3;
                int hh = idx >> 6, d = idx & 63;
                float* dst = (r == 0) ? g_q : (r == 1) ? g_k : g_v;
                dst[(hh * S_ + m) * DH_ + d] = v;
            } else if (MODE == 1) {
                g_h[m * DIM_ + n] += v;
            } else if (MODE == 2) {
                float t2 = v + bias[n];
                g_ff1[m * HID_ + n] = t2 > 0.f ? t2 : 0.2f * t2;
            } else {
                g_h[m * DIM_ + n] += v + bias[n];
            }
        }
    }
}

// ---------------- pb GEMM: g_pb[9600x64] = g_q @ g_rbT (256 thr, R9) ----------------
__global__ void __launch_bounds__(256) pb_gemm() {
    const float* A = g_q;
    const float* B = g_rbT;
    __shared__ __align__(16) float As[16][68];
    __shared__ __align__(16) float Bs[16][68];
    int tid = threadIdx.x;
    int tx = tid & 15, ty = tid >> 4;
    int m0 = blockIdx.y * 64;
    int arow = tid >> 2, acol = (tid & 3) * 4;
    int brow = tid >> 4, bcol = (tid & 15) * 4;
    float acc[4][4] = {};
    for (int k0 = 0; k0 < 64; k0 += 16) {
        float4 av = *reinterpret_cast<const float4*>(A + (size_t)(m0 + arow) * 64 + k0 + acol);
        As[acol+0][arow] = av.x; As[acol+1][arow] = av.y;
        As[acol+2][arow] = av.z; As[acol+3][arow] = av.w;
        float4 bv = *reinterpret_cast<const float4*>(B + (size_t)(k0 + brow) * 64 + bcol);
        *reinterpret_cast<float4*>(&Bs[brow][bcol]) = bv;
        __syncthreads();
#pragma unroll
        for (int kk = 0; kk < 16; kk++) {
            float4 a4 = *reinterpret_cast<const float4*>(&As[kk][ty*4]);
            float4 b4 = *reinterpret_cast<const float4*>(&Bs[kk][tx*4]);
            float ar[4] = {a4.x, a4.y, a4.z, a4.w};
            float br[4] = {b4.x, b4.y, b4.z, b4.w};
#pragma unroll
            for (int i = 0; i < 4; i++)
#pragma unroll
                for (int j = 0; j < 4; j++)
                    acc[i][j] = fmaf(ar[i], br[j], acc[i][j]);
        }
        __syncthreads();
    }
#pragma unroll
    for (int i = 0; i < 4; i++)
#pragma unroll
        for (int j = 0; j < 4; j++)
            g_pb[(m0 + ty*4 + i) * 64 + tx*4 + j] = acc[i][j];
}

// ---------------- scores via split-tf32 MMA (R9-proven) ----------------
__global__ void __launch_bounds__(256) scores_mma() {
    int h = blockIdx.z;
    const float* Q  = g_q + (size_t)h * S_ * DH_;
    const float* Km = g_k + (size_t)h * S_ * DH_;
    __shared__ __align__(16) float Qs[64][68];
    __shared__ __align__(16) float Ks[64][68];
    int tid = threadIdx.x;
    int m0 = blockIdx.y * 64, n0 = blockIdx.x * 64;
#pragma unroll
    for (int i = 0; i < 4; i++) {
        int e = tid + i * 256;
        int row = e >> 4, c = (e & 15) * 4;
        *reinterpret_cast<float4*>(&Qs[row][c]) =
            *reinterpret_cast<const float4*>(Q + (size_t)(m0 + row) * DH_ + c);
        *reinterpret_cast<float4*>(&Ks[row][c]) =
            *reinterpret_cast<const float4*>(Km + (size_t)(n0 + row) * DH_ + c);
    }
    __syncthreads();

    int wid = tid >> 5, lane = tid & 31;
    int wy = wid >> 1, wx = wid & 1;
    int gr = lane >> 2, tg = lane & 3;

    float acc[4][4] = {};
#pragma unroll
    for (int k0 = 0; k0 < 64; k0 += 8) {
        int ar = wy*16 + gr;
        float a[4];
        a[0] = Qs[ar    ][k0 + tg];
        a[1] = Qs[ar + 8][k0 + tg];
        a[2] = Qs[ar    ][k0 + tg + 4];
        a[3] = Qs[ar + 8][k0 + tg + 4];
        unsigned ah[4], al[4];
#pragma unroll
        for (int i = 0; i < 4; i++) {
            ah[i] = f2tf32(a[i]);
            al[i] = f2tf32(a[i] - __uint_as_float(ah[i]));
        }
#pragma unroll
        for (int t = 0; t < 4; t++) {
            int bn = wx*32 + t*8 + gr;
            float b0 = Ks[bn][k0 + tg];
            float b1 = Ks[bn][k0 + tg + 4];
            unsigned bh[2], bl[2];
            bh[0] = f2tf32(b0); bl[0] = f2tf32(b0 - __uint_as_float(bh[0]));
            bh[1] = f2tf32(b1); bl[1] = f2tf32(b1 - __uint_as_float(bh[1]));
            mma_tf32(acc[t], ah, bh);
            mma_tf32(acc[t], ah, bl);
            mma_tf32(acc[t], al, bh);
        }
    }
#pragma unroll
    for (int rr = 0; rr < 2; rr++) {
        int q = m0 + wy*16 + gr + rr*8;
        int qv = q / GW_, qh = q - qv * GW_;
        const float* pbq = g_pb + ((size_t)h * S_ + q) * 64;
        float pb0 = pbq[0];
        unsigned* srow = g_skey + ((size_t)h * S_ + q) * S_;
#pragma unroll
        for (int t = 0; t < 4; t++) {
            int kq0 = n0 + wx*32 + t*8 + tg*2;
            unsigned kb[2];
#pragma unroll
            for (int cc = 0; cc < 2; cc++) {
                int kq = kq0 + cc;
                int kv = kq / GW_, kh = kq - kv * GW_;
                int dv = kv - qv, dh = kh - qh;
                int ad = (dv < 0 ? -dv : dv) + (dh < 0 ? -dh : dh);
                float pbv = (ad <= 3) ? pbq[(dv + 3) * 7 + (dh + 3)] : pb0;
                float sc = (acc[t][rr*2 + cc] + pbv) * SCALE_;
                unsigned bts = __float_as_uint(sc);
                kb[cc] = (bts & 0x80000000u) ? ~bts : (bts | 0x80000000u);
            }
            *reinterpret_cast<uint2*>(srow + kq0) = make_uint2(kb[0], kb[1]);
        }
    }
}

// ---------------- attn_row: register keys + warp-aggregated hist + parallel select (R9-proven) ----------------
__global__ void __launch_bounds__(256) attn_row_kernel() {
    int bx = blockIdx.x;                 // h*S + q
    int h = bx / S_, q = bx - h * S_;
    const unsigned* srow = g_skey + (size_t)bx * S_;
    __shared__ unsigned hist[256];
    __shared__ unsigned sufw[8];
    __shared__ int   sidx[256];
    __shared__ float sval[256];
    __shared__ float pvred[4][DH_];
    __shared__ unsigned smaxw[8];
    __shared__ float ssum[8];
    __shared__ int sh_b, sh_k, sh_k2, sh_cnt;
    __shared__ float sh_inv;
    __shared__ unsigned sh_maxu;
    int tid = threadIdx.x;
    int wid = tid >> 5, lane = tid & 31;

    unsigned key[7];
    int nkk = (tid < 64) ? 7 : 6;
#pragma unroll
    for (int j = 0; j < 6; j++) key[j] = srow[tid + j*256];
    key[6] = (tid < 64) ? srow[tid + 1536] : 0u;

    unsigned mxu = 0u;
#pragma unroll
    for (int j = 0; j < 7; j++) mxu = max(mxu, key[j]);
    for (int o = 16; o; o >>= 1) mxu = max(mxu, __shfl_xor_sync(0xffffffffu, mxu, o));
    if (lane == 0) smaxw[wid] = mxu;
    if (tid == 0) { sh_k = TOPK_; sh_cnt = 0; }
    __syncthreads();
    if (tid == 0) {
        unsigned m = smaxw[0];
#pragma unroll
        for (int w = 1; w < 8; w++) m = max(m, smaxw[w]);
        sh_maxu = m;
    }

    unsigned pref = 0u;
    for (int shift = 24; shift >= 0; shift -= 8) {
        hist[tid] = 0u;
        __syncthreads();
        unsigned maskhi = (shift == 24) ? 0u : (0xFFFFFFFFu << (shift + 8));
        for (int j = 0; j < nkk; j++) {
            unsigned u = key[j];
            if ((u & maskhi) == pref) {
                unsigned b = (u >> shift) & 255u;
                unsigned act = __activemask();
                unsigned mmask = __match_any_sync(act, b);
                int leader = __ffs(mmask) - 1;
                if (lane == leader) atomicAdd(&hist[b], (unsigned)__popc(mmask));
            }
        }
        __syncthreads();
        unsigned c = hist[tid];
        unsigned s = c;
#pragma unroll
        for (int o = 1; o < 32; o <<= 1) {
            unsigned t = __shfl_down_sync(0xffffffffu, s, o);
            if (lane + o < 32) s += t;
        }
        if (lane == 0) sufw[wid] = s;
        __syncthreads();
        unsigned add = 0;
        for (int w = wid + 1; w < 8; w++) add += sufw[w];
        unsigned suf_incl = s + add;
        unsigned suf_excl = suf_incl - c;
        unsigned kkr = (unsigned)sh_k;
        if (suf_incl >= kkr && suf_excl < kkr) { sh_b = tid; sh_k2 = (int)(kkr - suf_excl); }
        __syncthreads();
        pref |= ((unsigned)sh_b) << shift;
        if (tid == 0) sh_k = sh_k2;
        __syncthreads();
    }
    unsigned thr = pref;
    unsigned mu = sh_maxu;
    float mxv = (mu & 0x80000000u) ? __uint_as_float(mu ^ 0x80000000u) : __uint_as_float(~mu);

    for (int j = 0; j < nkk; j++) {
        unsigned u = key[j];
        if (u >= thr) {
            int p = atomicAdd(&sh_cnt, 1);
            if (p < 256) {
                float v = (u & 0x80000000u) ? __uint_as_float(u ^ 0x80000000u)
                                            : __uint_as_float(~u);
                sidx[p] = tid + j*256;
                sval[p] = expf(v - mxv);
            }
        }
    }
    __syncthreads();
    int cnt = min(sh_cnt, 256);

    {
        float s = 0.f;
        for (int i = tid; i < cnt; i += 256) s += sval[i];
        for (int o = 16; o; o >>= 1) s += __shfl_xor_sync(0xffffffffu, s, o);
        if (lane == 0) ssum[wid] = s;
        __syncthreads();
        if (tid == 0) {
            float t = ssum[0];
#pragma unroll
            for (int w = 1; w < 8; w++) t += ssum[w];
            sh_inv = 1.f / t;
        }
        __syncthreads();
    }

    {
        int g = tid >> 6, d = tid & 63;
        const float* V = g_v + (size_t)h * S_ * DH_;
        float acc = 0.f;
        for (int i = g; i < cnt; i += 4) acc = fmaf(sval[i], V[sidx[i] * DH_ + d], acc);
        pvred[g][d] = acc;
        __syncthreads();
        if (tid < DH_) {
            float r = pvred[0][tid] + pvred[1][tid] + pvred[2][tid] + pvred[3][tid];
            g_att[q * INNER_ + h * DH_ + tid] = r * sh_inv;
        }
    }
}

// ---------------- host launcher ----------------
extern "C" void kernel_launch(void* const* d_in, const int* in_sizes, int n_in,
                              void* d_out, int out_size) {
    (void)in_sizes; (void)n_in; (void)out_size;
    const float* x    = (const float*)d_in[0];
    const float* Wqkv = (const float*)d_in[1];
    const float* Wo   = (const float*)d_in[2];
    const float* ln1g = (const float*)d_in[3];
    const float* ln1b = (const float*)d_in[4];
    const float* ln2g = (const float*)d_in[5];
    const float* ln2b = (const float*)d_in[6];
    const float* relb = (const float*)d_in[7];
    const float* w1   = (const float*)d_in[8];
    const float* b1   = (const float*)d_in[9];
    const float* w2   = (const float*)d_in[10];
    const float* b2   = (const float*)d_in[11];

    init_h_kernel<<<(S_*DIM_ + 255) / 256, 256>>>(x);
    rbT_kernel<<<16, 256>>>(relb);

    for (int l = 0; l < NL_; l++) {
        ln_kernel<<<S_, 128>>>(ln1g + l*DIM_, ln1b + l*DIM_);
        gemm64db<0><<<dim3(18, 25), 128>>>(Wqkv + (size_t)l*DIM_*3*INNER_, nullptr, 3*INNER_, DIM_);
        pb_gemm<<<dim3(1, (NH_*S_)/64), 256>>>();
        scores_mma<<<dim3(25, 25, NH_), 256>>>();
        attn_row_kernel<<<NH_*S_, 256>>>();
        gemm64db<1><<<dim3(6, 25), 128>>>(Wo + (size_t)l*INNER_*DIM_, nullptr, DIM_, INNER_);
        ln_kernel<<<S_, 128>>>(ln2g + l*DIM_, ln2b + l*DIM_);
        gemm64db<2><<<dim3(24, 25), 128>>>(w1 + (size_t)l*DIM_*HID_, b1 + l*HID_, HID_, DIM_);
        gemm64db<3><<<dim3(6, 25), 128>>>(w2 + (size_t)l*HID_*DIM_, b2 + l*DIM_, DIM_, HID_);
    }

    write_out_kernel<<<(S_*DIM_ + 255) / 256, 256>>>((float*)d_out);
}

// round 16
// speedup vs baseline: 1.1939x; 1.0328x over previous
#include <cuda_runtime.h>
#include <cuda_bf16.h>
#include <cstdint>
#include <float.h>

#define S_    1600
#define DIM_  384
#define NH_   6
#define DH_   64
#define INNER_ 384
#define HID_  1536
#define NL_   6
#define GW_   40
#define TOPK_ 32
#define SCALE_ 0.05103103630798288f   // 384^-0.5

// ---------------- device scratch ----------------
__device__ float g_h[S_*DIM_];
__device__ float g_n[S_*DIM_];
__device__ float g_q[NH_*S_*DH_];
__device__ float g_k[NH_*S_*DH_];
__device__ float g_v[NH_*S_*DH_];
__device__ float g_pb[NH_*S_*64];
__device__ float g_rbT[64*64];
__device__ unsigned g_skey[(long long)NH_*S_*S_];
__device__ float g_att[S_*INNER_];
__device__ float g_ff1[S_*HID_];

// ---------------- helpers ----------------
__device__ __forceinline__ void mma_bf16(float* c, const unsigned* a, const unsigned* b) {
    asm volatile(
        "mma.sync.aligned.m16n8k16.row.col.f32.bf16.bf16.f32 "
        "{%0,%1,%2,%3}, {%4,%5,%6,%7}, {%8,%9}, {%0,%1,%2,%3};"
        : "+f"(c[0]), "+f"(c[1]), "+f"(c[2]), "+f"(c[3])
        : "r"(a[0]), "r"(a[1]), "r"(a[2]), "r"(a[3]), "r"(b[0]), "r"(b[1]));
}
// pack two floats into bf16x2 (x0 -> low half), plus residual pack
__device__ __forceinline__ unsigned pack_hi(float x0, float x1) {
    __nv_bfloat162 t = __floats2bfloat162_rn(x0, x1);
    return *reinterpret_cast<unsigned*>(&t);
}
__device__ __forceinline__ unsigned pack_lo(float x0, float x1, unsigned hi) {
    __nv_bfloat162 h = *reinterpret_cast<__nv_bfloat162*>(&hi);
    __nv_bfloat162 t = __floats2bfloat162_rn(x0 - __bfloat162float(h.x),
                                             x1 - __bfloat162float(h.y));
    return *reinterpret_cast<unsigned*>(&t);
}

// ---------------- trivial kernels ----------------
__global__ void init_h_kernel(const float* __restrict__ x) {
    int i = blockIdx.x * blockDim.x + threadIdx.x;
    if (i < S_*DIM_) g_h[i] = x[i];
}
__global__ void write_out_kernel(float* __restrict__ out) {
    int i = blockIdx.x * blockDim.x + threadIdx.x;
    if (i < S_*DIM_) out[i] = g_h[i];
}
__global__ void rbT_kernel(const float* __restrict__ rb) {
    int i = blockIdx.x * blockDim.x + threadIdx.x;
    if (i < 64*64) {
        int d = i >> 6, m = i & 63;
        g_rbT[d*64 + m] = (m < 49) ? rb[m*64 + d] : 0.f;
    }
}

// ---------------- LayerNorm ----------------
__global__ void ln_kernel(const float* __restrict__ gamma, const float* __restrict__ beta) {
    int row = blockIdx.x;
    const float* x = g_h + row * DIM_;
    float s = 0.f, s2 = 0.f;
    for (int i = threadIdx.x; i < DIM_; i += blockDim.x) { float v = x[i]; s += v; s2 += v*v; }
    for (int o = 16; o; o >>= 1) {
        s  += __shfl_xor_sync(0xffffffffu, s,  o);
        s2 += __shfl_xor_sync(0xffffffffu, s2, o);
    }
    __shared__ float rs[4], rs2[4];
    int w = threadIdx.x >> 5;
    if ((threadIdx.x & 31) == 0) { rs[w] = s; rs2[w] = s2; }
    __syncthreads();
    s  = rs[0]  + rs[1]  + rs[2]  + rs[3];
    s2 = rs2[0] + rs2[1] + rs2[2] + rs2[3];
    float mean = s * (1.f / DIM_);
    float var  = s2 * (1.f / DIM_) - mean * mean;
    float inv  = rsqrtf(var + 1e-5f);
    for (int i = threadIdx.x; i < DIM_; i += blockDim.x)
        g_n[row*DIM_ + i] = (x[i] - mean) * inv * gamma[i] + beta[i];
}

// ========== double-buffered 64x64x16 SGEMM, 4x4 register tiles (R9-proven) ==========
template<int MODE>
__global__ void __launch_bounds__(256) gemm64db(const float* __restrict__ B,
                                                const float* __restrict__ bias,
                                                int N, int K) {
    const float* A = (MODE == 0 || MODE == 2) ? g_n : (MODE == 1 ? g_att : g_ff1);
    __shared__ __align__(16) float As[2][16][68];
    __shared__ __align__(16) float Bs[2][16][68];
    int tid = threadIdx.x;
    int tx = tid & 15, ty = tid >> 4;
    int m0 = blockIdx.y * 64, n0 = blockIdx.x * 64;
    int arow = tid >> 2, acol = (tid & 3) * 4;
    int brow = tid >> 4, bcol = (tid & 15) * 4;
    const int nk = K >> 4;
    {
        float4 av = *reinterpret_cast<const float4*>(A + (size_t)(m0 + arow) * K + acol);
        As[0][acol+0][arow] = av.x; As[0][acol+1][arow] = av.y;
        As[0][acol+2][arow] = av.z; As[0][acol+3][arow] = av.w;
        float4 bv = *reinterpret_cast<const float4*>(B + (size_t)brow * N + n0 + bcol);
        *reinterpret_cast<float4*>(&Bs[0][brow][bcol]) = bv;
    }
    __syncthreads();
    float acc[4][4] = {};
    for (int t = 0; t < nk; t++) {
        int cur = t & 1, nxt = cur ^ 1;
        float4 av, bv;
        bool more = (t + 1 < nk);
        if (more) {
            int k0 = (t + 1) << 4;
            av = *reinterpret_cast<const float4*>(A + (size_t)(m0 + arow) * K + k0 + acol);
            bv = *reinterpret_cast<const float4*>(B + (size_t)(k0 + brow) * N + n0 + bcol);
        }
#pragma unroll
        for (int kk = 0; kk < 16; kk++) {
            float4 a4 = *reinterpret_cast<const float4*>(&As[cur][kk][ty*4]);
            float4 b4 = *reinterpret_cast<const float4*>(&Bs[cur][kk][tx*4]);
            float ar[4] = {a4.x, a4.y, a4.z, a4.w};
            float br[4] = {b4.x, b4.y, b4.z, b4.w};
#pragma unroll
            for (int i = 0; i < 4; i++)
#pragma unroll
                for (int j = 0; j < 4; j++)
                    acc[i][j] = fmaf(ar[i], br[j], acc[i][j]);
        }
        if (more) {
            As[nxt][acol+0][arow] = av.x; As[nxt][acol+1][arow] = av.y;
            As[nxt][acol+2][arow] = av.z; As[nxt][acol+3][arow] = av.w;
            *reinterpret_cast<float4*>(&Bs[nxt][brow][bcol]) = bv;
        }
        __syncthreads();
    }
#pragma unroll
    for (int i = 0; i < 4; i++) {
        int m = m0 + ty*4 + i;
#pragma unroll
        for (int j = 0; j < 4; j++) {
            int n = n0 + tx*4 + j;
            float v = acc[i][j];
            if (MODE == 0) {
                int idx = n / 3, r = n - idx * 3;
                int hh = idx >> 6, d = idx & 63;
                float* dst = (r == 0) ? g_q : (r == 1) ? g_k : g_v;
                dst[(hh * S_ + m) * DH_ + d] = v;
            } else if (MODE == 1) {
                g_h[m * DIM_ + n] += v;
            } else if (MODE == 2) {
                float t2 = v + bias[n];
                g_ff1[m * HID_ + n] = t2 > 0.f ? t2 : 0.2f * t2;
            } else {
                g_h[m * DIM_ + n] += v + bias[n];
            }
        }
    }
}

// ---------------- pb GEMM (R9) ----------------
__global__ void __launch_bounds__(256) pb_gemm() {
    const float* A = g_q;
    const float* B = g_rbT;
    __shared__ __align__(16) float As[16][68];
    __shared__ __align__(16) float Bs[16][68];
    int tid = threadIdx.x;
    int tx = tid & 15, ty = tid >> 4;
    int m0 = blockIdx.y * 64;
    int arow = tid >> 2, acol = (tid & 3) * 4;
    int brow = tid >> 4, bcol = (tid & 15) * 4;
    float acc[4][4] = {};
    for (int k0 = 0; k0 < 64; k0 += 16) {
        float4 av = *reinterpret_cast<const float4*>(A + (size_t)(m0 + arow) * 64 + k0 + acol);
        As[acol+0][arow] = av.x; As[acol+1][arow] = av.y;
        As[acol+2][arow] = av.z; As[acol+3][arow] = av.w;
        float4 bv = *reinterpret_cast<const float4*>(B + (size_t)(k0 + brow) * 64 + bcol);
        *reinterpret_cast<float4*>(&Bs[brow][bcol]) = bv;
        __syncthreads();
#pragma unroll
        for (int kk = 0; kk < 16; kk++) {
            float4 a4 = *reinterpret_cast<const float4*>(&As[kk][ty*4]);
            float4 b4 = *reinterpret_cast<const float4*>(&Bs[kk][tx*4]);
            float ar[4] = {a4.x, a4.y, a4.z, a4.w};
            float br[4] = {b4.x, b4.y, b4.z, b4.w};
#pragma unroll
            for (int i = 0; i < 4; i++)
#pragma unroll
                for (int j = 0; j < 4; j++)
                    acc[i][j] = fmaf(ar[i], br[j], acc[i][j]);
        }
        __syncthreads();
    }
#pragma unroll
    for (int i = 0; i < 4; i++)
#pragma unroll
        for (int j = 0; j < 4; j++)
            g_pb[(m0 + ty*4 + i) * 64 + tx*4 + j] = acc[i][j];
}

// ---------------- scores via split-bf16 MMA (m16n8k16: half the instructions of tf32 path) ----------------
__global__ void __launch_bounds__(256) scores_mma() {
    int h = blockIdx.z;
    const float* Q  = g_q + (size_t)h * S_ * DH_;
    const float* Km = g_k + (size_t)h * S_ * DH_;
    __shared__ __align__(16) float Qs[64][68];
    __shared__ __align__(16) float Ks[64][68];
    int tid = threadIdx.x;
    int m0 = blockIdx.y * 64, n0 = blockIdx.x * 64;
#pragma unroll
    for (int i = 0; i < 4; i++) {
        int e = tid + i * 256;
        int row = e >> 4, c = (e & 15) * 4;
        *reinterpret_cast<float4*>(&Qs[row][c]) =
            *reinterpret_cast<const float4*>(Q + (size_t)(m0 + row) * DH_ + c);
        *reinterpret_cast<float4*>(&Ks[row][c]) =
            *reinterpret_cast<const float4*>(Km + (size_t)(n0 + row) * DH_ + c);
    }
    __syncthreads();

    int wid = tid >> 5, lane = tid & 31;
    int wy = wid >> 1, wx = wid & 1;
    int gr = lane >> 2, tg = lane & 3;

    float acc[4][4] = {};
#pragma unroll
    for (int k0 = 0; k0 < 64; k0 += 16) {
        int ar = wy*16 + gr;
        int kc = k0 + 2*tg;
        // A fragment (m16k16): 4 bf16x2 regs hi + lo
        float a00 = Qs[ar    ][kc],   a01 = Qs[ar    ][kc+1];
        float a10 = Qs[ar + 8][kc],   a11 = Qs[ar + 8][kc+1];
        float a20 = Qs[ar    ][kc+8], a21 = Qs[ar    ][kc+9];
        float a30 = Qs[ar + 8][kc+8], a31 = Qs[ar + 8][kc+9];
        unsigned ah[4], al[4];
        ah[0] = pack_hi(a00, a01); al[0] = pack_lo(a00, a01, ah[0]);
        ah[1] = pack_hi(a10, a11); al[1] = pack_lo(a10, a11, ah[1]);
        ah[2] = pack_hi(a20, a21); al[2] = pack_lo(a20, a21, ah[2]);
        ah[3] = pack_hi(a30, a31); al[3] = pack_lo(a30, a31, ah[3]);
#pragma unroll
        for (int t = 0; t < 4; t++) {
            int bn = wx*32 + t*8 + gr;
            float b00 = Ks[bn][kc],   b01 = Ks[bn][kc+1];
            float b10 = Ks[bn][kc+8], b11 = Ks[bn][kc+9];
            unsigned bh[2], bl[2];
            bh[0] = pack_hi(b00, b01); bl[0] = pack_lo(b00, b01, bh[0]);
            bh[1] = pack_hi(b10, b11); bl[1] = pack_lo(b10, b11, bh[1]);
            mma_bf16(acc[t], ah, bh);
            mma_bf16(acc[t], ah, bl);
            mma_bf16(acc[t], al, bh);
        }
    }
#pragma unroll
    for (int rr = 0; rr < 2; rr++) {
        int q = m0 + wy*16 + gr + rr*8;
        int qv = q / GW_, qh = q - qv * GW_;
        const float* pbq = g_pb + ((size_t)h * S_ + q) * 64;
        float pb0 = pbq[0];
        unsigned* srow = g_skey + ((size_t)h * S_ + q) * S_;
#pragma unroll
        for (int t = 0; t < 4; t++) {
            int kq0 = n0 + wx*32 + t*8 + tg*2;
            unsigned kb[2];
#pragma unroll
            for (int cc = 0; cc < 2; cc++) {
                int kq = kq0 + cc;
                int kv = kq / GW_, kh = kq - kv * GW_;
                int dv = kv - qv, dh = kh - qh;
                int ad = (dv < 0 ? -dv : dv) + (dh < 0 ? -dh : dh);
                float pbv = (ad <= 3) ? pbq[(dv + 3) * 7 + (dh + 3)] : pb0;
                float sc = (acc[t][rr*2 + cc] + pbv) * SCALE_;
                unsigned bts = __float_as_uint(sc);
                kb[cc] = (bts & 0x80000000u) ? ~bts : (bts | 0x80000000u);
            }
            *reinterpret_cast<uint2*>(srow + kq0) = make_uint2(kb[0], kb[1]);
        }
    }
}

// ---------------- attn_row: register keys + warp-aggregated hist + parallel select (R9-proven) ----------------
__global__ void __launch_bounds__(256) attn_row_kernel() {
    int bx = blockIdx.x;                 // h*S + q
    int h = bx / S_, q = bx - h * S_;
    const unsigned* srow = g_skey + (size_t)bx * S_;
    __shared__ unsigned hist[256];
    __shared__ unsigned sufw[8];
    __shared__ int   sidx[256];
    __shared__ float sval[256];
    __shared__ float pvred[4][DH_];
    __shared__ unsigned smaxw[8];
    __shared__ float ssum[8];
    __shared__ int sh_b, sh_k, sh_k2, sh_cnt;
    __shared__ float sh_inv;
    __shared__ unsigned sh_maxu;
    int tid = threadIdx.x;
    int wid = tid >> 5, lane = tid & 31;

    unsigned key[7];
    int nkk = (tid < 64) ? 7 : 6;
#pragma unroll
    for (int j = 0; j < 6; j++) key[j] = srow[tid + j*256];
    key[6] = (tid < 64) ? srow[tid + 1536] : 0u;

    unsigned mxu = 0u;
#pragma unroll
    for (int j = 0; j < 7; j++) mxu = max(mxu, key[j]);
    for (int o = 16; o; o >>= 1) mxu = max(mxu, __shfl_xor_sync(0xffffffffu, mxu, o));
    if (lane == 0) smaxw[wid] = mxu;
    if (tid == 0) { sh_k = TOPK_; sh_cnt = 0; }
    __syncthreads();
    if (tid == 0) {
        unsigned m = smaxw[0];
#pragma unroll
        for (int w = 1; w < 8; w++) m = max(m, smaxw[w]);
        sh_maxu = m;
    }

    unsigned pref = 0u;
    for (int shift = 24; shift >= 0; shift -= 8) {
        hist[tid] = 0u;
        __syncthreads();
        unsigned maskhi = (shift == 24) ? 0u : (0xFFFFFFFFu << (shift + 8));
        for (int j = 0; j < nkk; j++) {
            unsigned u = key[j];
            if ((u & maskhi) == pref) {
                unsigned b = (u >> shift) & 255u;
                unsigned act = __activemask();
                unsigned mmask = __match_any_sync(act, b);
                int leader = __ffs(mmask) - 1;
                if (lane == leader) atomicAdd(&hist[b], (unsigned)__popc(mmask));
            }
        }
        __syncthreads();
        unsigned c = hist[tid];
        unsigned s = c;
#pragma unroll
        for (int o = 1; o < 32; o <<= 1) {
            unsigned t = __shfl_down_sync(0xffffffffu, s, o);
            if (lane + o < 32) s += t;
        }
        if (lane == 0) sufw[wid] = s;
        __syncthreads();
        unsigned add = 0;
        for (int w = wid + 1; w < 8; w++) add += sufw[w];
        unsigned suf_incl = s + add;
        unsigned suf_excl = suf_incl - c;
        unsigned kkr = (unsigned)sh_k;
        if (suf_incl >= kkr && suf_excl < kkr) { sh_b = tid; sh_k2 = (int)(kkr - suf_excl); }
        __syncthreads();
        pref |= ((unsigned)sh_b) << shift;
        if (tid == 0) sh_k = sh_k2;
        __syncthreads();
    }
    unsigned thr = pref;
    unsigned mu = sh_maxu;
    float mxv = (mu & 0x80000000u) ? __uint_as_float(mu ^ 0x80000000u) : __uint_as_float(~mu);

    for (int j = 0; j < nkk; j++) {
        unsigned u = key[j];
        if (u >= thr) {
            int p = atomicAdd(&sh_cnt, 1);
            if (p < 256) {
                float v = (u & 0x80000000u) ? __uint_as_float(u ^ 0x80000000u)
                                            : __uint_as_float(~u);
                sidx[p] = tid + j*256;
                sval[p] = expf(v - mxv);
            }
        }
    }
    __syncthreads();
    int cnt = min(sh_cnt, 256);

    {
        float s = 0.f;
        for (int i = tid; i < cnt; i += 256) s += sval[i];
        for (int o = 16; o; o >>= 1) s += __shfl_xor_sync(0xffffffffu, s, o);
        if (lane == 0) ssum[wid] = s;
        __syncthreads();
        if (tid == 0) {
            float t = ssum[0];
#pragma unroll
            for (int w = 1; w < 8; w++) t += ssum[w];
            sh_inv = 1.f / t;
        }
        __syncthreads();
    }

    {
        int g = tid >> 6, d = tid & 63;
        const float* V = g_v + (size_t)h * S_ * DH_;
        float acc = 0.f;
        for (int i = g; i < cnt; i += 4) acc = fmaf(sval[i], V[sidx[i] * DH_ + d], acc);
        pvred[g][d] = acc;
        __syncthreads();
        if (tid < DH_) {
            float r = pvred[0][tid] + pvred[1][tid] + pvred[2][tid] + pvred[3][tid];
            g_att[q * INNER_ + h * DH_ + tid] = r * sh_inv;
        }
    }
}

// ---------------- host launcher ----------------
extern "C" void kernel_launch(void* const* d_in, const int* in_sizes, int n_in,
                              void* d_out, int out_size) {
    (void)in_sizes; (void)n_in; (void)out_size;
    const float* x    = (const float*)d_in[0];
    const float* Wqkv = (const float*)d_in[1];
    const float* Wo   = (const float*)d_in[2];
    const float* ln1g = (const float*)d_in[3];
    const float* ln1b = (const float*)d_in[4];
    const float* ln2g = (const float*)d_in[5];
    const float* ln2b = (const float*)d_in[6];
    const float* relb = (const float*)d_in[7];
    const float* w1   = (const float*)d_in[8];
    const float* b1   = (const float*)d_in[9];
    const float* w2   = (const float*)d_in[10];
    const float* b2   = (const float*)d_in[11];

    init_h_kernel<<<(S_*DIM_ + 255) / 256, 256>>>(x);
    rbT_kernel<<<16, 256>>>(relb);

    for (int l = 0; l < NL_; l++) {
        ln_kernel<<<S_, 128>>>(ln1g + l*DIM_, ln1b + l*DIM_);
        gemm64db<0><<<dim3(18, 25), 256>>>(Wqkv + (size_t)l*DIM_*3*INNER_, nullptr, 3*INNER_, DIM_);
        pb_gemm<<<dim3(1, (NH_*S_)/64), 256>>>();
        scores_mma<<<dim3(25, 25, NH_), 256>>>();
        attn_row_kernel<<<NH_*S_, 256>>>();
        gemm64db<1><<<dim3(6, 25), 256>>>(Wo + (size_t)l*INNER_*DIM_, nullptr, DIM_, INNER_);
        ln_kernel<<<S_, 128>>>(ln2g + l*DIM_, ln2b + l*DIM_);
        gemm64db<2><<<dim3(24, 25), 256>>>(w1 + (size_t)l*DIM_*HID_, b1 + l*HID_, HID_, DIM_);
        gemm64db<3><<<dim3(6, 25), 256>>>(w2 + (size_t)l*HID_*DIM_, b2 + l*DIM_, DIM_, HID_);
    }

    write_out_kernel<<<(S_*DIM_ + 255) / 256, 256>>>((float*)d_out);
}